// round 3
// baseline (speedup 1.0000x reference)
#include <cuda_runtime.h>

// ---------------- problem constants ----------------
#define NMAX 100000
#define GMAX 2048
#define HEADS 4

// ---------------- scratch (device globals; no allocation allowed) ----------------
__device__ __align__(16) float    g_h1[NMAX * 64];
__device__ __align__(16) float    g_als1[NMAX * 4];
__device__ __align__(16) float    g_ald1[NMAX * 4];
__device__ __align__(16) unsigned g_m1[NMAX * 4];
__device__ __align__(16) float    g_den1[NMAX * 4];
__device__ __align__(16) float    g_agg1[NMAX * 64];
__device__ __align__(16) float    g_x2[NMAX * 64];
__device__ __align__(16) float    g_h2[NMAX * 128];
__device__ __align__(16) float    g_als2[NMAX * 4];
__device__ __align__(16) float    g_ald2[NMAX * 4];
__device__ __align__(16) unsigned g_m2[NMAX * 4];
__device__ __align__(16) float    g_den2[NMAX * 4];
__device__ __align__(16) float    g_agg2[NMAX * 128];
__device__ __align__(16) float    g_sums[GMAX * 128];
__device__ __align__(16) float    g_cnt[GMAX];

// ---------------- helpers ----------------
__device__ __forceinline__ unsigned fkey(float f) {
    unsigned u = __float_as_uint(f);
    return (u & 0x80000000u) ? ~u : (u | 0x80000000u);
}
__device__ __forceinline__ float fdec(unsigned u) {
    return __uint_as_float((u & 0x80000000u) ? (u ^ 0x80000000u) : ~u);
}
__device__ __forceinline__ void red4(float* p, float a, float b, float c, float d) {
    asm volatile("red.global.add.v4.f32 [%0], {%1,%2,%3,%4};"
                 :: "l"(p), "f"(a), "f"(b), "f"(c), "f"(d) : "memory");
}
__device__ __forceinline__ float lrelu(float e) { return e > 0.f ? e : 0.2f * e; }

// ---------------- GEMM 1: h1 = x[N,128] @ W1[128,64] ----------------
__global__ void k_gemm1(const float* __restrict__ x, const float* __restrict__ W, int N) {
    __shared__ float sW[128 * 64];
    for (int i = threadIdx.x; i < 128 * 64; i += 256) sW[i] = W[i];
    __syncthreads();
    int col = threadIdx.x & 63;
    int rl  = threadIdx.x >> 6;          // 0..3
    int rowBase = blockIdx.x * 16;
    for (int rb = 0; rb < 4; rb++) {
        int row = rowBase + rb * 4 + rl;
        if (row < N) {
            const float4* xr = (const float4*)(x + (size_t)row * 128);
            float acc = 0.f;
#pragma unroll
            for (int k4 = 0; k4 < 32; k4++) {
                float4 xv = __ldg(&xr[k4]);
                acc = fmaf(xv.x, sW[(k4 * 4 + 0) * 64 + col], acc);
                acc = fmaf(xv.y, sW[(k4 * 4 + 1) * 64 + col], acc);
                acc = fmaf(xv.z, sW[(k4 * 4 + 2) * 64 + col], acc);
                acc = fmaf(xv.w, sW[(k4 * 4 + 3) * 64 + col], acc);
            }
            g_h1[(size_t)row * 64 + col] = acc;
        }
    }
}

// ---------------- GEMM 2: h2 = x2[N,64] @ W2[64,128] ----------------
__global__ void k_gemm2(const float* __restrict__ W, int N) {
    __shared__ float sW[64 * 128];
    for (int i = threadIdx.x; i < 64 * 128; i += 256) sW[i] = W[i];
    __syncthreads();
    int col = threadIdx.x & 127;
    int rl  = threadIdx.x >> 7;          // 0..1
    int rowBase = blockIdx.x * 8;
    for (int rb = 0; rb < 4; rb++) {
        int row = rowBase + rb * 2 + rl;
        if (row < N) {
            const float4* xr = (const float4*)(g_x2 + (size_t)row * 64);
            float acc = 0.f;
#pragma unroll
            for (int k4 = 0; k4 < 16; k4++) {
                float4 xv = xr[k4];
                acc = fmaf(xv.x, sW[(k4 * 4 + 0) * 128 + col], acc);
                acc = fmaf(xv.y, sW[(k4 * 4 + 1) * 128 + col], acc);
                acc = fmaf(xv.z, sW[(k4 * 4 + 2) * 128 + col], acc);
                acc = fmaf(xv.w, sW[(k4 * 4 + 3) * 128 + col], acc);
            }
            g_h2[(size_t)row * 128 + col] = acc;
        }
    }
}

// ---------------- attention logits: al[n,h] = <h[n,h,:], a[h,:]> ----------------
__global__ void k_al(const float* __restrict__ h, const float* __restrict__ a_s,
                     const float* __restrict__ a_d, float* __restrict__ als,
                     float* __restrict__ ald, int N, int C) {
    int t = blockIdx.x * blockDim.x + threadIdx.x;
    if (t >= N * 4) return;
    int n = t >> 2, head = t & 3;
    const float* hp = h + (size_t)n * (4 * C) + head * C;
    const float* as = a_s + head * C;
    const float* ad = a_d + head * C;
    float s = 0.f, d = 0.f;
    for (int c = 0; c < C; c++) {
        float v = hp[c];
        s = fmaf(v, as[c], s);
        d = fmaf(v, ad[c], d);
    }
    als[t] = s;
    ald[t] = d;
}

// ---------------- segment max over incoming edges ----------------
__global__ void k_max(const int* __restrict__ ei, const float* __restrict__ als,
                      const float* __restrict__ ald, unsigned* __restrict__ m,
                      int E, int N) {
    int t = blockIdx.x * blockDim.x + threadIdx.x;
    if (t >= E + N) return;
    int s, d;
    if (t < E) { s = ei[t]; d = ei[(size_t)E + t]; }
    else       { s = d = t - E; }
    float4 a = *(const float4*)(als + (size_t)s * 4);
    float4 b = *(const float4*)(ald + (size_t)d * 4);
    float e[4] = { lrelu(a.x + b.x), lrelu(a.y + b.y), lrelu(a.z + b.z), lrelu(a.w + b.w) };
#pragma unroll
    for (int h = 0; h < 4; h++) {
        unsigned k = fkey(e[h]);
        unsigned* p = &m[(size_t)d * 4 + h];
        if (k > __ldcg(p)) atomicMax(p, k);
    }
}

// ---------------- exp-sum + weighted scatter, layer 1 (64 feats, 16 thr/edge) ----
__global__ void k_sum1(const int* __restrict__ ei, int E, int N) {
    int gt = blockIdx.x * 256 + threadIdx.x;
    int idx = gt >> 4;
    int lane = gt & 15;
    if (idx >= E + N) return;
    int s, d;
    if (idx < E) { s = ei[idx]; d = ei[(size_t)E + idx]; }
    else         { s = d = idx - E; }
    int head = lane >> 2;
    float e = g_als1[(size_t)s * 4 + head] + g_ald1[(size_t)d * 4 + head];
    e = lrelu(e);
    float mx = fdec(g_m1[(size_t)d * 4 + head]);
    float ex = __expf(e - mx);
    if ((lane & 3) == 0) atomicAdd(&g_den1[(size_t)d * 4 + head], ex);
    float4 hv = *(const float4*)(g_h1 + (size_t)s * 64 + lane * 4);
    red4(g_agg1 + (size_t)d * 64 + lane * 4, ex * hv.x, ex * hv.y, ex * hv.z, ex * hv.w);
}

// ---------------- exp-sum + weighted scatter, layer 2 (128 feats, 32 thr/edge) ---
__global__ void k_sum2(const int* __restrict__ ei, int E, int N) {
    int gt = blockIdx.x * 256 + threadIdx.x;
    int idx = gt >> 5;
    int lane = gt & 31;
    if (idx >= E + N) return;
    int s, d;
    if (idx < E) { s = ei[idx]; d = ei[(size_t)E + idx]; }
    else         { s = d = idx - E; }
    int head = lane >> 3;
    float e = g_als2[(size_t)s * 4 + head] + g_ald2[(size_t)d * 4 + head];
    e = lrelu(e);
    float mx = fdec(g_m2[(size_t)d * 4 + head]);
    float ex = __expf(e - mx);
    if ((lane & 7) == 0) atomicAdd(&g_den2[(size_t)d * 4 + head], ex);
    float4 hv = *(const float4*)(g_h2 + (size_t)s * 128 + lane * 4);
    red4(g_agg2 + (size_t)d * 128 + lane * 4, ex * hv.x, ex * hv.y, ex * hv.z, ex * hv.w);
}

// ---------------- finalize layer 1: x2 = relu(agg/den + b1) ----------------
__global__ void k_fin1(const float* __restrict__ b1, int N) {
    int t = blockIdx.x * blockDim.x + threadIdx.x;   // one float4 per thread
    if (t >= N * 16) return;
    int n = t >> 4, c4 = t & 15;
    int head = c4 >> 2;
    float inv = 1.f / (g_den1[(size_t)n * 4 + head] + 1e-16f);
    float4 ag = *(const float4*)(g_agg1 + (size_t)t * 4);
    float4 bb = *(const float4*)(b1 + c4 * 4);
    float4 o;
    o.x = fmaxf(ag.x * inv + bb.x, 0.f);
    o.y = fmaxf(ag.y * inv + bb.y, 0.f);
    o.z = fmaxf(ag.z * inv + bb.z, 0.f);
    o.w = fmaxf(ag.w * inv + bb.w, 0.f);
    *(float4*)(g_x2 + (size_t)t * 4) = o;
}

// ---------------- finalize layer 2 + pooled sums ----------------
__global__ void k_fin2pool(const float* __restrict__ b2, const int* __restrict__ batch, int N) {
    int t = blockIdx.x * blockDim.x + threadIdx.x;   // one float4 per thread
    if (t >= N * 32) return;
    int n = t >> 5, c4 = t & 31;
    int head = c4 >> 3;
    int g = batch[n];
    float inv = 1.f / (g_den2[(size_t)n * 4 + head] + 1e-16f);
    float4 ag = *(const float4*)(g_agg2 + (size_t)t * 4);
    float4 bb = *(const float4*)(b2 + c4 * 4);
    float4 o;
    o.x = fmaxf(ag.x * inv + bb.x, 0.f);
    o.y = fmaxf(ag.y * inv + bb.y, 0.f);
    o.z = fmaxf(ag.z * inv + bb.z, 0.f);
    o.w = fmaxf(ag.w * inv + bb.w, 0.f);
    red4(g_sums + (size_t)g * 128 + c4 * 4, o.x, o.y, o.z, o.w);
    if (c4 == 0) atomicAdd(&g_cnt[g], 1.f);
}

// ---------------- pool divide ----------------
__global__ void k_pool(float* __restrict__ out, int G) {
    int t = blockIdx.x * blockDim.x + threadIdx.x;   // one float4 per thread
    if (t >= G * 32) return;
    int g = t >> 5;
    float inv = 1.f / fmaxf(g_cnt[g], 1.f);
    float4 s = *(const float4*)(g_sums + (size_t)t * 4);
    float4 o = { s.x * inv, s.y * inv, s.z * inv, s.w * inv };
    *(float4*)(out + (size_t)t * 4) = o;
}

// ---------------- launch ----------------
extern "C" void kernel_launch(void* const* d_in, const int* in_sizes, int n_in,
                              void* d_out, int out_size) {
    const float* x     = (const float*)d_in[0];
    const int*   ei    = (const int*)d_in[1];     // int32 (JAX x64 disabled)
    // d_in[2] = edge_attr (unused)
    const int*   batch = (const int*)d_in[3];     // int32
    const float* W1    = (const float*)d_in[4];
    const float* a_s1  = (const float*)d_in[5];
    const float* a_d1  = (const float*)d_in[6];
    const float* b1    = (const float*)d_in[7];
    const float* W2    = (const float*)d_in[8];
    const float* a_s2  = (const float*)d_in[9];
    const float* a_d2  = (const float*)d_in[10];
    const float* b2    = (const float*)d_in[11];
    float*       out   = (float*)d_out;

    int N = in_sizes[0] / 128;
    int E = in_sizes[1] / 2;
    int G = out_size / 128;
    int T = E + N;   // edges incl. self loops

    // --- reset per-replay state (m-keys: 0 is below any real key) ---
    void *pm1, *pd1, *pa1, *pm2, *pd2, *pa2, *ps, *pc;
    cudaGetSymbolAddress(&pm1, g_m1);   cudaGetSymbolAddress(&pd1, g_den1);
    cudaGetSymbolAddress(&pa1, g_agg1); cudaGetSymbolAddress(&pm2, g_m2);
    cudaGetSymbolAddress(&pd2, g_den2); cudaGetSymbolAddress(&pa2, g_agg2);
    cudaGetSymbolAddress(&ps,  g_sums); cudaGetSymbolAddress(&pc,  g_cnt);
    cudaMemsetAsync(pm1, 0, (size_t)N * 4 * 4);
    cudaMemsetAsync(pd1, 0, (size_t)N * 4 * 4);
    cudaMemsetAsync(pa1, 0, (size_t)N * 64 * 4);
    cudaMemsetAsync(pm2, 0, (size_t)N * 4 * 4);
    cudaMemsetAsync(pd2, 0, (size_t)N * 4 * 4);
    cudaMemsetAsync(pa2, 0, (size_t)N * 128 * 4);
    cudaMemsetAsync(ps,  0, (size_t)G * 128 * 4);
    cudaMemsetAsync(pc,  0, (size_t)G * 4);

    float *h1p, *h2p;
    cudaGetSymbolAddress((void**)&h1p, g_h1);
    cudaGetSymbolAddress((void**)&h2p, g_h2);
    float *als1p, *ald1p, *als2p, *ald2p;
    cudaGetSymbolAddress((void**)&als1p, g_als1);
    cudaGetSymbolAddress((void**)&ald1p, g_ald1);
    cudaGetSymbolAddress((void**)&als2p, g_als2);
    cudaGetSymbolAddress((void**)&ald2p, g_ald2);
    unsigned *m1p, *m2p;
    cudaGetSymbolAddress((void**)&m1p, g_m1);
    cudaGetSymbolAddress((void**)&m2p, g_m2);

    // --- layer 1 ---
    k_gemm1<<<(N + 15) / 16, 256>>>(x, W1, N);
    k_al<<<(N * 4 + 255) / 256, 256>>>(h1p, a_s1, a_d1, als1p, ald1p, N, 16);
    k_max<<<(T + 255) / 256, 256>>>(ei, als1p, ald1p, m1p, E, N);
    k_sum1<<<(T + 15) / 16, 256>>>(ei, E, N);
    k_fin1<<<(N * 16 + 255) / 256, 256>>>(b1, N);

    // --- layer 2 ---
    k_gemm2<<<(N + 7) / 8, 256>>>(W2, N);
    k_al<<<(N * 4 + 255) / 256, 256>>>(h2p, a_s2, a_d2, als2p, ald2p, N, 32);
    k_max<<<(T + 255) / 256, 256>>>(ei, als2p, ald2p, m2p, E, N);
    k_sum2<<<(T + 7) / 8, 256>>>(ei, E, N);
    k_fin2pool<<<(N * 32 + 255) / 256, 256>>>(b2, batch, N);

    // --- pool ---
    k_pool<<<(G * 32 + 255) / 256, 256>>>(out, G);
}

// round 4
// speedup vs baseline: 1.4018x; 1.4018x over previous
#include <cuda_runtime.h>

// ---------------- problem constants ----------------
#define NMAX 100000
#define GMAX 2048
#define EMAXT 3301024   // E + N + margin

// ---------------- scratch (device globals; no allocation allowed) ----------------
__device__ __align__(16) float g_h1[NMAX * 64];
__device__ __align__(16) float g_als1[NMAX * 4];
__device__ __align__(16) float g_ald1[NMAX * 4];
__device__ __align__(16) float g_x2[NMAX * 64];
__device__ __align__(16) float g_h2[NMAX * 128];
__device__ __align__(16) float g_als2[NMAX * 4];
__device__ __align__(16) float g_ald2[NMAX * 4];
__device__ __align__(16) float g_sums[GMAX * 128];
__device__ __align__(16) float g_cnt[GMAX];
// CSR
__device__ int g_deg[NMAX];
__device__ int g_rs[NMAX + 1];
__device__ int g_cur[NMAX];
__device__ int g_esrc[EMAXT];
__device__ int g_bs[512];

// ---------------- helpers ----------------
__device__ __forceinline__ float lrelu(float e) { return e > 0.f ? e : 0.2f * e; }
__device__ __forceinline__ void red4(float* p, float a, float b, float c, float d) {
    asm volatile("red.global.add.v4.f32 [%0], {%1,%2,%3,%4};"
                 :: "l"(p), "f"(a), "f"(b), "f"(c), "f"(d) : "memory");
}

// ---------------- CSR build ----------------
__global__ void k_deg(const int* __restrict__ ei, int E, int N) {
    int t = blockIdx.x * blockDim.x + threadIdx.x;
    if (t >= E + N) return;
    int d = (t < E) ? ei[(size_t)E + t] : t - E;
    atomicAdd(&g_deg[d], 1);
}

__global__ void k_s1(int N) {
    __shared__ int sh[256];
    int t = threadIdx.x;
    int i = blockIdx.x * 256 + t;
    int v = (i < N) ? g_deg[i] : 0;
    sh[t] = v;
    __syncthreads();
    for (int o = 1; o < 256; o <<= 1) {
        int add = (t >= o) ? sh[t - o] : 0;
        __syncthreads();
        sh[t] += add;
        __syncthreads();
    }
    if (i < N) g_rs[i] = sh[t] - v;             // exclusive
    if (t == 255) g_bs[blockIdx.x] = sh[255];   // block total
}

__global__ void k_s2(int nb) {
    __shared__ int sh[512];
    int t = threadIdx.x;
    int v = (t < nb) ? g_bs[t] : 0;
    sh[t] = v;
    __syncthreads();
    for (int o = 1; o < 512; o <<= 1) {
        int add = (t >= o) ? sh[t - o] : 0;
        __syncthreads();
        sh[t] += add;
        __syncthreads();
    }
    if (t < nb) g_bs[t] = sh[t] - v;            // exclusive
}

__global__ void k_s3(int N, int T) {
    int i = blockIdx.x * 256 + threadIdx.x;
    if (i < N) {
        int v = g_rs[i] + g_bs[blockIdx.x];
        g_rs[i] = v;
        g_cur[i] = v;
    }
    if (i == N) g_rs[N] = T;
}

__global__ void k_fill(const int* __restrict__ ei, int E, int N) {
    int t = blockIdx.x * blockDim.x + threadIdx.x;
    if (t >= E + N) return;
    int s, d;
    if (t < E) { s = ei[t]; d = ei[(size_t)E + t]; }
    else       { s = d = t - E; }
    int pos = atomicAdd(&g_cur[d], 1);
    g_esrc[pos] = s;
}

// ---------------- GEMM 1: h1 = x[N,128] @ W1[128,64] ----------------
__global__ void k_gemm1(const float* __restrict__ x, const float* __restrict__ W, int N) {
    __shared__ float sW[128 * 64];
    for (int i = threadIdx.x; i < 128 * 64; i += 256) sW[i] = W[i];
    __syncthreads();
    int col = threadIdx.x & 63;
    int rl  = threadIdx.x >> 6;
    int rowBase = blockIdx.x * 16;
    for (int rb = 0; rb < 4; rb++) {
        int row = rowBase + rb * 4 + rl;
        if (row < N) {
            const float4* xr = (const float4*)(x + (size_t)row * 128);
            float acc = 0.f;
#pragma unroll
            for (int k4 = 0; k4 < 32; k4++) {
                float4 xv = __ldg(&xr[k4]);
                acc = fmaf(xv.x, sW[(k4 * 4 + 0) * 64 + col], acc);
                acc = fmaf(xv.y, sW[(k4 * 4 + 1) * 64 + col], acc);
                acc = fmaf(xv.z, sW[(k4 * 4 + 2) * 64 + col], acc);
                acc = fmaf(xv.w, sW[(k4 * 4 + 3) * 64 + col], acc);
            }
            g_h1[(size_t)row * 64 + col] = acc;
        }
    }
}

// ---------------- GEMM 2: h2 = x2[N,64] @ W2[64,128] ----------------
__global__ void k_gemm2(const float* __restrict__ W, int N) {
    __shared__ float sW[64 * 128];
    for (int i = threadIdx.x; i < 64 * 128; i += 256) sW[i] = W[i];
    __syncthreads();
    int col = threadIdx.x & 127;
    int rl  = threadIdx.x >> 7;
    int rowBase = blockIdx.x * 8;
    for (int rb = 0; rb < 4; rb++) {
        int row = rowBase + rb * 2 + rl;
        if (row < N) {
            const float4* xr = (const float4*)(g_x2 + (size_t)row * 64);
            float acc = 0.f;
#pragma unroll
            for (int k4 = 0; k4 < 16; k4++) {
                float4 xv = xr[k4];
                acc = fmaf(xv.x, sW[(k4 * 4 + 0) * 128 + col], acc);
                acc = fmaf(xv.y, sW[(k4 * 4 + 1) * 128 + col], acc);
                acc = fmaf(xv.z, sW[(k4 * 4 + 2) * 128 + col], acc);
                acc = fmaf(xv.w, sW[(k4 * 4 + 3) * 128 + col], acc);
            }
            g_h2[(size_t)row * 128 + col] = acc;
        }
    }
}

// ---------------- attention logits ----------------
__global__ void k_al(const float* __restrict__ h, const float* __restrict__ a_s,
                     const float* __restrict__ a_d, float* __restrict__ als,
                     float* __restrict__ ald, int N, int C) {
    int t = blockIdx.x * blockDim.x + threadIdx.x;
    if (t >= N * 4) return;
    int n = t >> 2, head = t & 3;
    const float* hp = h + (size_t)n * (4 * C) + head * C;
    const float* as = a_s + head * C;
    const float* ad = a_d + head * C;
    float s = 0.f, d = 0.f;
    for (int c = 0; c < C; c++) {
        float v = hp[c];
        s = fmaf(v, as[c], s);
        d = fmaf(v, ad[c], d);
    }
    als[t] = s;
    ald[t] = d;
}

// ---------------- fused layer-1 aggregation: one warp per node ----------------
// max -> exp/den -> weighted sum of h1[src] -> /den + bias -> relu -> x2
__global__ void k_agg1(const float* __restrict__ b1, int N) {
    int w = (blockIdx.x * blockDim.x + threadIdx.x) >> 5;
    int lane = threadIdx.x & 31;
    if (w >= N) return;
    int n = w;
    int start = g_rs[n], end = g_rs[n + 1];
    float4 ad = *(const float4*)(g_ald1 + (size_t)n * 4);

    // phase 1: per-head max over incoming edges
    float4 mx = make_float4(-3e38f, -3e38f, -3e38f, -3e38f);
    for (int base = start; base < end; base += 32) {
        int i = base + lane;
        if (i < end) {
            int s = g_esrc[i];
            float4 a = *(const float4*)(g_als1 + (size_t)s * 4);
            mx.x = fmaxf(mx.x, lrelu(a.x + ad.x));
            mx.y = fmaxf(mx.y, lrelu(a.y + ad.y));
            mx.z = fmaxf(mx.z, lrelu(a.z + ad.z));
            mx.w = fmaxf(mx.w, lrelu(a.w + ad.w));
        }
    }
#pragma unroll
    for (int o = 16; o; o >>= 1) {
        mx.x = fmaxf(mx.x, __shfl_xor_sync(0xffffffffu, mx.x, o));
        mx.y = fmaxf(mx.y, __shfl_xor_sync(0xffffffffu, mx.y, o));
        mx.z = fmaxf(mx.z, __shfl_xor_sync(0xffffffffu, mx.z, o));
        mx.w = fmaxf(mx.w, __shfl_xor_sync(0xffffffffu, mx.w, o));
    }

    // phase 2: exp, denominator, weighted accumulation (feats lane*2, lane*2+1)
    int head = lane >> 3;   // (lane*2)/16
    float acc0 = 0.f, acc1 = 0.f;
    float4 den = make_float4(0.f, 0.f, 0.f, 0.f);
    for (int base = start; base < end; base += 32) {
        int i = base + lane;
        int cnt = min(32, end - base);
        int s = 0;
        float4 ex = make_float4(0.f, 0.f, 0.f, 0.f);
        if (i < end) {
            s = g_esrc[i];
            float4 a = *(const float4*)(g_als1 + (size_t)s * 4);
            ex.x = __expf(lrelu(a.x + ad.x) - mx.x);
            ex.y = __expf(lrelu(a.y + ad.y) - mx.y);
            ex.z = __expf(lrelu(a.z + ad.z) - mx.z);
            ex.w = __expf(lrelu(a.w + ad.w) - mx.w);
            den.x += ex.x; den.y += ex.y; den.z += ex.z; den.w += ex.w;
        }
        for (int j = 0; j < cnt; j++) {
            int   sj = __shfl_sync(0xffffffffu, s, j);
            float e0 = __shfl_sync(0xffffffffu, ex.x, j);
            float e1 = __shfl_sync(0xffffffffu, ex.y, j);
            float e2 = __shfl_sync(0xffffffffu, ex.z, j);
            float e3 = __shfl_sync(0xffffffffu, ex.w, j);
            float exm = (head == 0) ? e0 : ((head == 1) ? e1 : ((head == 2) ? e2 : e3));
            float2 hv = *(const float2*)(g_h1 + (size_t)sj * 64 + lane * 2);
            acc0 = fmaf(exm, hv.x, acc0);
            acc1 = fmaf(exm, hv.y, acc1);
        }
    }
#pragma unroll
    for (int o = 16; o; o >>= 1) {
        den.x += __shfl_xor_sync(0xffffffffu, den.x, o);
        den.y += __shfl_xor_sync(0xffffffffu, den.y, o);
        den.z += __shfl_xor_sync(0xffffffffu, den.z, o);
        den.w += __shfl_xor_sync(0xffffffffu, den.w, o);
    }
    float dh = (head == 0) ? den.x : ((head == 1) ? den.y : ((head == 2) ? den.z : den.w));
    float inv = 1.f / (dh + 1e-16f);
    float2 o2;
    o2.x = fmaxf(acc0 * inv + b1[lane * 2], 0.f);
    o2.y = fmaxf(acc1 * inv + b1[lane * 2 + 1], 0.f);
    *(float2*)(g_x2 + (size_t)n * 64 + lane * 2) = o2;
}

// ---------------- fused layer-2 aggregation + pooled sums ----------------
__global__ void k_agg2(const float* __restrict__ b2, const int* __restrict__ batch, int N) {
    int w = (blockIdx.x * blockDim.x + threadIdx.x) >> 5;
    int lane = threadIdx.x & 31;
    if (w >= N) return;
    int n = w;
    int start = g_rs[n], end = g_rs[n + 1];
    float4 ad = *(const float4*)(g_ald2 + (size_t)n * 4);

    float4 mx = make_float4(-3e38f, -3e38f, -3e38f, -3e38f);
    for (int base = start; base < end; base += 32) {
        int i = base + lane;
        if (i < end) {
            int s = g_esrc[i];
            float4 a = *(const float4*)(g_als2 + (size_t)s * 4);
            mx.x = fmaxf(mx.x, lrelu(a.x + ad.x));
            mx.y = fmaxf(mx.y, lrelu(a.y + ad.y));
            mx.z = fmaxf(mx.z, lrelu(a.z + ad.z));
            mx.w = fmaxf(mx.w, lrelu(a.w + ad.w));
        }
    }
#pragma unroll
    for (int o = 16; o; o >>= 1) {
        mx.x = fmaxf(mx.x, __shfl_xor_sync(0xffffffffu, mx.x, o));
        mx.y = fmaxf(mx.y, __shfl_xor_sync(0xffffffffu, mx.y, o));
        mx.z = fmaxf(mx.z, __shfl_xor_sync(0xffffffffu, mx.z, o));
        mx.w = fmaxf(mx.w, __shfl_xor_sync(0xffffffffu, mx.w, o));
    }

    int head = lane >> 3;   // (lane*4)/32
    float acc0 = 0.f, acc1 = 0.f, acc2 = 0.f, acc3 = 0.f;
    float4 den = make_float4(0.f, 0.f, 0.f, 0.f);
    for (int base = start; base < end; base += 32) {
        int i = base + lane;
        int cnt = min(32, end - base);
        int s = 0;
        float4 ex = make_float4(0.f, 0.f, 0.f, 0.f);
        if (i < end) {
            s = g_esrc[i];
            float4 a = *(const float4*)(g_als2 + (size_t)s * 4);
            ex.x = __expf(lrelu(a.x + ad.x) - mx.x);
            ex.y = __expf(lrelu(a.y + ad.y) - mx.y);
            ex.z = __expf(lrelu(a.z + ad.z) - mx.z);
            ex.w = __expf(lrelu(a.w + ad.w) - mx.w);
            den.x += ex.x; den.y += ex.y; den.z += ex.z; den.w += ex.w;
        }
        for (int j = 0; j < cnt; j++) {
            int   sj = __shfl_sync(0xffffffffu, s, j);
            float e0 = __shfl_sync(0xffffffffu, ex.x, j);
            float e1 = __shfl_sync(0xffffffffu, ex.y, j);
            float e2 = __shfl_sync(0xffffffffu, ex.z, j);
            float e3 = __shfl_sync(0xffffffffu, ex.w, j);
            float exm = (head == 0) ? e0 : ((head == 1) ? e1 : ((head == 2) ? e2 : e3));
            float4 hv = *(const float4*)(g_h2 + (size_t)sj * 128 + lane * 4);
            acc0 = fmaf(exm, hv.x, acc0);
            acc1 = fmaf(exm, hv.y, acc1);
            acc2 = fmaf(exm, hv.z, acc2);
            acc3 = fmaf(exm, hv.w, acc3);
        }
    }
#pragma unroll
    for (int o = 16; o; o >>= 1) {
        den.x += __shfl_xor_sync(0xffffffffu, den.x, o);
        den.y += __shfl_xor_sync(0xffffffffu, den.y, o);
        den.z += __shfl_xor_sync(0xffffffffu, den.z, o);
        den.w += __shfl_xor_sync(0xffffffffu, den.w, o);
    }
    float dh = (head == 0) ? den.x : ((head == 1) ? den.y : ((head == 2) ? den.z : den.w));
    float inv = 1.f / (dh + 1e-16f);
    const float4 bb = *(const float4*)(b2 + lane * 4);
    float o0 = fmaxf(acc0 * inv + bb.x, 0.f);
    float o1 = fmaxf(acc1 * inv + bb.y, 0.f);
    float o2 = fmaxf(acc2 * inv + bb.z, 0.f);
    float o3 = fmaxf(acc3 * inv + bb.w, 0.f);
    int g = batch[n];
    red4(g_sums + (size_t)g * 128 + lane * 4, o0, o1, o2, o3);
    if (lane == 0) atomicAdd(&g_cnt[g], 1.f);
}

// ---------------- pool divide ----------------
__global__ void k_pool(float* __restrict__ out, int G) {
    int t = blockIdx.x * blockDim.x + threadIdx.x;
    if (t >= G * 32) return;
    int g = t >> 5;
    float inv = 1.f / fmaxf(g_cnt[g], 1.f);
    float4 s = *(const float4*)(g_sums + (size_t)t * 4);
    float4 o = { s.x * inv, s.y * inv, s.z * inv, s.w * inv };
    *(float4*)(out + (size_t)t * 4) = o;
}

// ---------------- launch ----------------
extern "C" void kernel_launch(void* const* d_in, const int* in_sizes, int n_in,
                              void* d_out, int out_size) {
    const float* x     = (const float*)d_in[0];
    const int*   ei    = (const int*)d_in[1];
    // d_in[2] = edge_attr (unused)
    const int*   batch = (const int*)d_in[3];
    const float* W1    = (const float*)d_in[4];
    const float* a_s1  = (const float*)d_in[5];
    const float* a_d1  = (const float*)d_in[6];
    const float* b1    = (const float*)d_in[7];
    const float* W2    = (const float*)d_in[8];
    const float* a_s2  = (const float*)d_in[9];
    const float* a_d2  = (const float*)d_in[10];
    const float* b2    = (const float*)d_in[11];
    float*       out   = (float*)d_out;

    int N = in_sizes[0] / 128;
    int E = in_sizes[1] / 2;
    int G = out_size / 128;
    int T = E + N;

    void *pdeg, *ps, *pc;
    cudaGetSymbolAddress(&pdeg, g_deg);
    cudaGetSymbolAddress(&ps, g_sums);
    cudaGetSymbolAddress(&pc, g_cnt);
    cudaMemsetAsync(pdeg, 0, (size_t)N * 4);
    cudaMemsetAsync(ps, 0, (size_t)G * 128 * 4);
    cudaMemsetAsync(pc, 0, (size_t)G * 4);

    float *h1p, *h2p, *als1p, *ald1p, *als2p, *ald2p;
    cudaGetSymbolAddress((void**)&h1p, g_h1);
    cudaGetSymbolAddress((void**)&h2p, g_h2);
    cudaGetSymbolAddress((void**)&als1p, g_als1);
    cudaGetSymbolAddress((void**)&ald1p, g_ald1);
    cudaGetSymbolAddress((void**)&als2p, g_als2);
    cudaGetSymbolAddress((void**)&ald2p, g_ald2);

    int nb = (N + 255) / 256;

    // --- CSR build (dst-grouped) ---
    k_deg<<<(T + 255) / 256, 256>>>(ei, E, N);
    k_s1<<<nb, 256>>>(N);
    k_s2<<<1, 512>>>(nb);
    k_s3<<<(N + 256) / 256, 256>>>(N, T);
    k_fill<<<(T + 255) / 256, 256>>>(ei, E, N);

    // --- layer 1 ---
    k_gemm1<<<(N + 15) / 16, 256>>>(x, W1, N);
    k_al<<<(N * 4 + 255) / 256, 256>>>(h1p, a_s1, a_d1, als1p, ald1p, N, 16);
    k_agg1<<<(N + 7) / 8, 256>>>(b1, N);

    // --- layer 2 ---
    k_gemm2<<<(N + 7) / 8, 256>>>(W2, N);
    k_al<<<(N * 4 + 255) / 256, 256>>>(h2p, a_s2, a_d2, als2p, ald2p, N, 32);
    k_agg2<<<(N + 7) / 8, 256>>>(b2, batch, N);

    // --- pool ---
    k_pool<<<(G * 32 + 255) / 256, 256>>>(out, G);
}

// round 6
// speedup vs baseline: 1.9149x; 1.3660x over previous
#include <cuda_runtime.h>

// ---------------- problem constants ----------------
#define NMAX 100000
#define GMAX 2048
#define EMAXT 3301024   // E + N + margin

// ---------------- scratch (device globals; no allocation allowed) ----------------
__device__ __align__(16) float g_h1[NMAX * 64];
__device__ __align__(16) float g_als1[NMAX * 4];
__device__ __align__(16) float g_ald1[NMAX * 4];
__device__ __align__(16) float g_x2[NMAX * 64];
__device__ __align__(16) float g_h2[NMAX * 128];
__device__ __align__(16) float g_als2[NMAX * 4];
__device__ __align__(16) float g_ald2[NMAX * 4];
__device__ __align__(16) float g_sums[GMAX * 128];
__device__ __align__(16) float g_cnt[GMAX];
// CSR
__device__ int g_deg[NMAX];
__device__ int g_rs[NMAX + 1];
__device__ int g_cur[NMAX];
__device__ int g_esrc[EMAXT];
__device__ int g_bs[512];

// ---------------- helpers ----------------
__device__ __forceinline__ float lrelu(float e) { return e > 0.f ? e : 0.2f * e; }
__device__ __forceinline__ void red4(float* p, float a, float b, float c, float d) {
    asm volatile("red.global.add.v4.f32 [%0], {%1,%2,%3,%4};"
                 :: "l"(p), "f"(a), "f"(b), "f"(c), "f"(d) : "memory");
}

// ---------------- CSR build ----------------
__global__ void k_deg(const int* __restrict__ ei, int E, int N) {
    int t = blockIdx.x * blockDim.x + threadIdx.x;
    if (t >= E + N) return;
    int d = (t < E) ? ei[(size_t)E + t] : t - E;
    atomicAdd(&g_deg[d], 1);
}

__global__ void k_s1(int N) {
    __shared__ int sh[256];
    int t = threadIdx.x;
    int i = blockIdx.x * 256 + t;
    int v = (i < N) ? g_deg[i] : 0;
    sh[t] = v;
    __syncthreads();
    for (int o = 1; o < 256; o <<= 1) {
        int add = (t >= o) ? sh[t - o] : 0;
        __syncthreads();
        sh[t] += add;
        __syncthreads();
    }
    if (i < N) g_rs[i] = sh[t] - v;
    if (t == 255) g_bs[blockIdx.x] = sh[255];
}

__global__ void k_s2(int nb) {
    __shared__ int sh[512];
    int t = threadIdx.x;
    int v = (t < nb) ? g_bs[t] : 0;
    sh[t] = v;
    __syncthreads();
    for (int o = 1; o < 512; o <<= 1) {
        int add = (t >= o) ? sh[t - o] : 0;
        __syncthreads();
        sh[t] += add;
        __syncthreads();
    }
    if (t < nb) g_bs[t] = sh[t] - v;
}

__global__ void k_s3(int N, int T) {
    int i = blockIdx.x * 256 + threadIdx.x;
    if (i < N) {
        int v = g_rs[i] + g_bs[blockIdx.x];
        g_rs[i] = v;
        g_cur[i] = v;
    }
    if (i == N) g_rs[N] = T;
}

__global__ void k_fill(const int* __restrict__ ei, int E, int N) {
    int t = blockIdx.x * blockDim.x + threadIdx.x;
    if (t >= E + N) return;
    int s, d;
    if (t < E) { s = ei[t]; d = ei[(size_t)E + t]; }
    else       { s = d = t - E; }
    int pos = atomicAdd(&g_cur[d], 1);
    g_esrc[pos] = s;
}

// ---------------- GEMM 1 + fused attention logits ----------------
// h1 = x[N,128] @ W1[128,64]; als1/ald1 via half-warp (16-lane = head) reduce
__global__ void k_gemm1(const float* __restrict__ x, const float* __restrict__ W,
                        const float* __restrict__ a_s, const float* __restrict__ a_d, int N) {
    __shared__ float sW[128 * 64];
    for (int i = threadIdx.x; i < 128 * 64; i += 256) sW[i] = W[i];
    __syncthreads();
    int col = threadIdx.x & 63;
    int rl  = threadIdx.x >> 6;
    float asv = a_s[col];   // a[head][c] flattened == a[col]
    float adv = a_d[col];
    int head = col >> 4;
    int rowBase = blockIdx.x * 16;
    for (int rb = 0; rb < 4; rb++) {
        int row = rowBase + rb * 4 + rl;
        if (row < N) {
            const float4* xr = (const float4*)(x + (size_t)row * 128);
            float acc = 0.f;
#pragma unroll
            for (int k4 = 0; k4 < 32; k4++) {
                float4 xv = __ldg(&xr[k4]);
                acc = fmaf(xv.x, sW[(k4 * 4 + 0) * 64 + col], acc);
                acc = fmaf(xv.y, sW[(k4 * 4 + 1) * 64 + col], acc);
                acc = fmaf(xv.z, sW[(k4 * 4 + 2) * 64 + col], acc);
                acc = fmaf(xv.w, sW[(k4 * 4 + 3) * 64 + col], acc);
            }
            g_h1[(size_t)row * 64 + col] = acc;
            float s = acc * asv, d = acc * adv;
#pragma unroll
            for (int o = 8; o; o >>= 1) {
                s += __shfl_xor_sync(0xffffffffu, s, o);
                d += __shfl_xor_sync(0xffffffffu, d, o);
            }
            if ((col & 15) == 0) {
                g_als1[(size_t)row * 4 + head] = s;
                g_ald1[(size_t)row * 4 + head] = d;
            }
        }
    }
}

// ---------------- GEMM 2 + fused attention logits ----------------
// h2 = x2[N,64] @ W2[64,128]; warp (32-lane = head) reduce
__global__ void k_gemm2(const float* __restrict__ W,
                        const float* __restrict__ a_s, const float* __restrict__ a_d, int N) {
    __shared__ float sW[64 * 128];
    for (int i = threadIdx.x; i < 64 * 128; i += 256) sW[i] = W[i];
    __syncthreads();
    int col = threadIdx.x & 127;
    int rl  = threadIdx.x >> 7;
    float asv = a_s[col];
    float adv = a_d[col];
    int head = col >> 5;
    int rowBase = blockIdx.x * 8;
    for (int rb = 0; rb < 4; rb++) {
        int row = rowBase + rb * 2 + rl;
        if (row < N) {
            const float4* xr = (const float4*)(g_x2 + (size_t)row * 64);
            float acc = 0.f;
#pragma unroll
            for (int k4 = 0; k4 < 16; k4++) {
                float4 xv = xr[k4];
                acc = fmaf(xv.x, sW[(k4 * 4 + 0) * 128 + col], acc);
                acc = fmaf(xv.y, sW[(k4 * 4 + 1) * 128 + col], acc);
                acc = fmaf(xv.z, sW[(k4 * 4 + 2) * 128 + col], acc);
                acc = fmaf(xv.w, sW[(k4 * 4 + 3) * 128 + col], acc);
            }
            g_h2[(size_t)row * 128 + col] = acc;
            float s = acc * asv, d = acc * adv;
#pragma unroll
            for (int o = 16; o; o >>= 1) {
                s += __shfl_xor_sync(0xffffffffu, s, o);
                d += __shfl_xor_sync(0xffffffffu, d, o);
            }
            if ((col & 31) == 0) {
                g_als2[(size_t)row * 4 + head] = s;
                g_ald2[(size_t)row * 4 + head] = d;
            }
        }
    }
}

// ---------------- fused layer-1 aggregation: one warp per node ----------------
__global__ void k_agg1(const float* __restrict__ b1, int N) {
    __shared__ int   sh_idx[8][32];
    __shared__ float sh_ex[8][32 * 4];
    int wid = threadIdx.x >> 5;
    int w = (blockIdx.x * blockDim.x + threadIdx.x) >> 5;
    int lane = threadIdx.x & 31;
    if (w >= N) return;
    int n = w;
    int start = g_rs[n], end = g_rs[n + 1];
    float4 ad = *(const float4*)(g_ald1 + (size_t)n * 4);

    // phase 1: per-head max
    float4 mx = make_float4(-3e38f, -3e38f, -3e38f, -3e38f);
    for (int base = start; base < end; base += 32) {
        int i = base + lane;
        if (i < end) {
            int s = g_esrc[i];
            float4 a = *(const float4*)(g_als1 + (size_t)s * 4);
            mx.x = fmaxf(mx.x, lrelu(a.x + ad.x));
            mx.y = fmaxf(mx.y, lrelu(a.y + ad.y));
            mx.z = fmaxf(mx.z, lrelu(a.z + ad.z));
            mx.w = fmaxf(mx.w, lrelu(a.w + ad.w));
        }
    }
#pragma unroll
    for (int o = 16; o; o >>= 1) {
        mx.x = fmaxf(mx.x, __shfl_xor_sync(0xffffffffu, mx.x, o));
        mx.y = fmaxf(mx.y, __shfl_xor_sync(0xffffffffu, mx.y, o));
        mx.z = fmaxf(mx.z, __shfl_xor_sync(0xffffffffu, mx.z, o));
        mx.w = fmaxf(mx.w, __shfl_xor_sync(0xffffffffu, mx.w, o));
    }

    // phase 2: exp/den + weighted sum; feats lane*2, lane*2+1
    int head = lane >> 3;
    float acc0 = 0.f, acc1 = 0.f;
    float4 den = make_float4(0.f, 0.f, 0.f, 0.f);
    for (int base = start; base < end; base += 32) {
        int i = base + lane;
        int cnt = min(32, end - base);
        int s = 0;
        float4 ex = make_float4(0.f, 0.f, 0.f, 0.f);
        if (i < end) {
            s = g_esrc[i];
            float4 a = *(const float4*)(g_als1 + (size_t)s * 4);
            ex.x = __expf(lrelu(a.x + ad.x) - mx.x);
            ex.y = __expf(lrelu(a.y + ad.y) - mx.y);
            ex.z = __expf(lrelu(a.z + ad.z) - mx.z);
            ex.w = __expf(lrelu(a.w + ad.w) - mx.w);
            den.x += ex.x; den.y += ex.y; den.z += ex.z; den.w += ex.w;
        }
        sh_idx[wid][lane] = s;
        *(float4*)&sh_ex[wid][lane * 4] = ex;
        __syncwarp();
        if (cnt == 32) {
#pragma unroll 8
            for (int j = 0; j < 32; j++) {
                int   sj  = sh_idx[wid][j];
                float exm = sh_ex[wid][j * 4 + head];
                float2 hv = *(const float2*)(g_h1 + (size_t)sj * 64 + lane * 2);
                acc0 = fmaf(exm, hv.x, acc0);
                acc1 = fmaf(exm, hv.y, acc1);
            }
        } else {
            for (int j = 0; j < cnt; j++) {
                int   sj  = sh_idx[wid][j];
                float exm = sh_ex[wid][j * 4 + head];
                float2 hv = *(const float2*)(g_h1 + (size_t)sj * 64 + lane * 2);
                acc0 = fmaf(exm, hv.x, acc0);
                acc1 = fmaf(exm, hv.y, acc1);
            }
        }
        __syncwarp();
    }
#pragma unroll
    for (int o = 16; o; o >>= 1) {
        den.x += __shfl_xor_sync(0xffffffffu, den.x, o);
        den.y += __shfl_xor_sync(0xffffffffu, den.y, o);
        den.z += __shfl_xor_sync(0xffffffffu, den.z, o);
        den.w += __shfl_xor_sync(0xffffffffu, den.w, o);
    }
    float dh = (head == 0) ? den.x : ((head == 1) ? den.y : ((head == 2) ? den.z : den.w));
    float inv = 1.f / (dh + 1e-16f);
    float2 o2;
    o2.x = fmaxf(acc0 * inv + b1[lane * 2], 0.f);
    o2.y = fmaxf(acc1 * inv + b1[lane * 2 + 1], 0.f);
    *(float2*)(g_x2 + (size_t)n * 64 + lane * 2) = o2;
}

// ---------------- fused layer-2 aggregation + pooled sums ----------------
__global__ void k_agg2(const float* __restrict__ b2, const int* __restrict__ batch, int N) {
    __shared__ int   sh_idx[8][32];
    __shared__ float sh_ex[8][32 * 4];
    int wid = threadIdx.x >> 5;
    int w = (blockIdx.x * blockDim.x + threadIdx.x) >> 5;
    int lane = threadIdx.x & 31;
    if (w >= N) return;
    int n = w;
    int start = g_rs[n], end = g_rs[n + 1];
    float4 ad = *(const float4*)(g_ald2 + (size_t)n * 4);

    float4 mx = make_float4(-3e38f, -3e38f, -3e38f, -3e38f);
    for (int base = start; base < end; base += 32) {
        int i = base + lane;
        if (i < end) {
            int s = g_esrc[i];
            float4 a = *(const float4*)(g_als2 + (size_t)s * 4);
            mx.x = fmaxf(mx.x, lrelu(a.x + ad.x));
            mx.y = fmaxf(mx.y, lrelu(a.y + ad.y));
            mx.z = fmaxf(mx.z, lrelu(a.z + ad.z));
            mx.w = fmaxf(mx.w, lrelu(a.w + ad.w));
        }
    }
#pragma unroll
    for (int o = 16; o; o >>= 1) {
        mx.x = fmaxf(mx.x, __shfl_xor_sync(0xffffffffu, mx.x, o));
        mx.y = fmaxf(mx.y, __shfl_xor_sync(0xffffffffu, mx.y, o));
        mx.z = fmaxf(mx.z, __shfl_xor_sync(0xffffffffu, mx.z, o));
        mx.w = fmaxf(mx.w, __shfl_xor_sync(0xffffffffu, mx.w, o));
    }

    int head = lane >> 3;
    float acc0 = 0.f, acc1 = 0.f, acc2 = 0.f, acc3 = 0.f;
    float4 den = make_float4(0.f, 0.f, 0.f, 0.f);
    for (int base = start; base < end; base += 32) {
        int i = base + lane;
        int cnt = min(32, end - base);
        int s = 0;
        float4 ex = make_float4(0.f, 0.f, 0.f, 0.f);
        if (i < end) {
            s = g_esrc[i];
            float4 a = *(const float4*)(g_als2 + (size_t)s * 4);
            ex.x = __expf(lrelu(a.x + ad.x) - mx.x);
            ex.y = __expf(lrelu(a.y + ad.y) - mx.y);
            ex.z = __expf(lrelu(a.z + ad.z) - mx.z);
            ex.w = __expf(lrelu(a.w + ad.w) - mx.w);
            den.x += ex.x; den.y += ex.y; den.z += ex.z; den.w += ex.w;
        }
        sh_idx[wid][lane] = s;
        *(float4*)&sh_ex[wid][lane * 4] = ex;
        __syncwarp();
        if (cnt == 32) {
#pragma unroll 4
            for (int j = 0; j < 32; j++) {
                int   sj  = sh_idx[wid][j];
                float exm = sh_ex[wid][j * 4 + head];
                float4 hv = *(const float4*)(g_h2 + (size_t)sj * 128 + lane * 4);
                acc0 = fmaf(exm, hv.x, acc0);
                acc1 = fmaf(exm, hv.y, acc1);
                acc2 = fmaf(exm, hv.z, acc2);
                acc3 = fmaf(exm, hv.w, acc3);
            }
        } else {
            for (int j = 0; j < cnt; j++) {
                int   sj  = sh_idx[wid][j];
                float exm = sh_ex[wid][j * 4 + head];
                float4 hv = *(const float4*)(g_h2 + (size_t)sj * 128 + lane * 4);
                acc0 = fmaf(exm, hv.x, acc0);
                acc1 = fmaf(exm, hv.y, acc1);
                acc2 = fmaf(exm, hv.z, acc2);
                acc3 = fmaf(exm, hv.w, acc3);
            }
        }
        __syncwarp();
    }
#pragma unroll
    for (int o = 16; o; o >>= 1) {
        den.x += __shfl_xor_sync(0xffffffffu, den.x, o);
        den.y += __shfl_xor_sync(0xffffffffu, den.y, o);
        den.z += __shfl_xor_sync(0xffffffffu, den.z, o);
        den.w += __shfl_xor_sync(0xffffffffu, den.w, o);
    }
    float dh = (head == 0) ? den.x : ((head == 1) ? den.y : ((head == 2) ? den.z : den.w));
    float inv = 1.f / (dh + 1e-16f);
    const float4 bb = *(const float4*)(b2 + lane * 4);
    float o0 = fmaxf(acc0 * inv + bb.x, 0.f);
    float o1 = fmaxf(acc1 * inv + bb.y, 0.f);
    float o2 = fmaxf(acc2 * inv + bb.z, 0.f);
    float o3 = fmaxf(acc3 * inv + bb.w, 0.f);
    int g = batch[n];
    red4(g_sums + (size_t)g * 128 + lane * 4, o0, o1, o2, o3);
    if (lane == 0) atomicAdd(&g_cnt[g], 1.f);
}

// ---------------- pool divide ----------------
__global__ void k_pool(float* __restrict__ out, int G) {
    int t = blockIdx.x * blockDim.x + threadIdx.x;
    if (t >= G * 32) return;
    int g = t >> 5;
    float inv = 1.f / fmaxf(g_cnt[g], 1.f);
    float4 s = *(const float4*)(g_sums + (size_t)t * 4);
    float4 o = { s.x * inv, s.y * inv, s.z * inv, s.w * inv };
    *(float4*)(out + (size_t)t * 4) = o;
}

// ---------------- launch ----------------
extern "C" void kernel_launch(void* const* d_in, const int* in_sizes, int n_in,
                              void* d_out, int out_size) {
    const float* x     = (const float*)d_in[0];
    const int*   ei    = (const int*)d_in[1];
    const int*   batch = (const int*)d_in[3];
    const float* W1    = (const float*)d_in[4];
    const float* a_s1  = (const float*)d_in[5];
    const float* a_d1  = (const float*)d_in[6];
    const float* b1    = (const float*)d_in[7];
    const float* W2    = (const float*)d_in[8];
    const float* a_s2  = (const float*)d_in[9];
    const float* a_d2  = (const float*)d_in[10];
    const float* b2    = (const float*)d_in[11];
    float*       out   = (float*)d_out;

    int N = in_sizes[0] / 128;
    int E = in_sizes[1] / 2;
    int G = out_size / 128;
    int T = E + N;

    void *pdeg, *ps, *pc;
    cudaGetSymbolAddress(&pdeg, g_deg);
    cudaGetSymbolAddress(&ps, g_sums);
    cudaGetSymbolAddress(&pc, g_cnt);
    cudaMemsetAsync(pdeg, 0, (size_t)N * 4);
    cudaMemsetAsync(ps, 0, (size_t)G * 128 * 4);
    cudaMemsetAsync(pc, 0, (size_t)G * 4);

    int nb = (N + 255) / 256;

    // --- CSR build (dst-grouped) ---
    k_deg<<<(T + 255) / 256, 256>>>(ei, E, N);
    k_s1<<<nb, 256>>>(N);
    k_s2<<<1, 512>>>(nb);
    k_s3<<<(N + 256) / 256, 256>>>(N, T);
    k_fill<<<(T + 255) / 256, 256>>>(ei, E, N);

    // --- layer 1 ---
    k_gemm1<<<(N + 15) / 16, 256>>>(x, W1, a_s1, a_d1, N);
    k_agg1<<<(N + 7) / 8, 256>>>(b1, N);

    // --- layer 2 ---
    k_gemm2<<<(N + 7) / 8, 256>>>(W2, a_s2, a_d2, N);
    k_agg2<<<(N + 7) / 8, 256>>>(b2, batch, N);

    // --- pool ---
    k_pool<<<(G * 32 + 255) / 256, 256>>>(out, G);
}

// round 7
// speedup vs baseline: 2.6753x; 1.3971x over previous
#include <cuda_runtime.h>

// ---------------- problem constants ----------------
#define NMAX 100000
#define GMAX 2048
#define EMAXT 3301024   // E + N + margin

// ---------------- scratch (device globals; no allocation allowed) ----------------
__device__ __align__(16) float g_h1[NMAX * 64];
__device__ __align__(16) float g_als1[NMAX * 4];
__device__ __align__(16) float g_ald1[NMAX * 4];
__device__ __align__(16) float g_x2[NMAX * 64];
__device__ __align__(16) float g_h2[NMAX * 128];
__device__ __align__(16) float g_als2[NMAX * 4];
__device__ __align__(16) float g_ald2[NMAX * 4];
__device__ __align__(16) float g_sums[GMAX * 128];
__device__ __align__(16) float g_cnt[GMAX];
// CSR
__device__ int g_deg[NMAX];
__device__ int g_rs[NMAX + 1];
__device__ int g_cur[NMAX];
__device__ int g_esrc[EMAXT];
__device__ int g_bs[512];

// ---------------- helpers ----------------
__device__ __forceinline__ float lrelu(float e) { return e > 0.f ? e : 0.2f * e; }
__device__ __forceinline__ void red4(float* p, float a, float b, float c, float d) {
    asm volatile("red.global.add.v4.f32 [%0], {%1,%2,%3,%4};"
                 :: "l"(p), "f"(a), "f"(b), "f"(c), "f"(d) : "memory");
}

// ---------------- CSR build ----------------
__global__ void k_deg(const int* __restrict__ ei, int E, int N) {
    int t = blockIdx.x * blockDim.x + threadIdx.x;
    if (t >= E + N) return;
    int d = (t < E) ? ei[(size_t)E + t] : t - E;
    atomicAdd(&g_deg[d], 1);
}

__global__ void k_s1(int N) {
    __shared__ int sh[256];
    int t = threadIdx.x;
    int i = blockIdx.x * 256 + t;
    int v = (i < N) ? g_deg[i] : 0;
    sh[t] = v;
    __syncthreads();
    for (int o = 1; o < 256; o <<= 1) {
        int add = (t >= o) ? sh[t - o] : 0;
        __syncthreads();
        sh[t] += add;
        __syncthreads();
    }
    if (i < N) g_rs[i] = sh[t] - v;
    if (t == 255) g_bs[blockIdx.x] = sh[255];
}

__global__ void k_s2(int nb) {
    __shared__ int sh[512];
    int t = threadIdx.x;
    int v = (t < nb) ? g_bs[t] : 0;
    sh[t] = v;
    __syncthreads();
    for (int o = 1; o < 512; o <<= 1) {
        int add = (t >= o) ? sh[t - o] : 0;
        __syncthreads();
        sh[t] += add;
        __syncthreads();
    }
    if (t < nb) g_bs[t] = sh[t] - v;
}

__global__ void k_s3(int N, int T) {
    int i = blockIdx.x * 256 + threadIdx.x;
    if (i < N) {
        int v = g_rs[i] + g_bs[blockIdx.x];
        g_rs[i] = v;
        g_cur[i] = v;
    }
    if (i == N) g_rs[N] = T;
}

__global__ void k_fill(const int* __restrict__ ei, int E, int N) {
    int t = blockIdx.x * blockDim.x + threadIdx.x;
    if (t >= E + N) return;
    int s, d;
    if (t < E) { s = ei[t]; d = ei[(size_t)E + t]; }
    else       { s = d = t - E; }
    int pos = atomicAdd(&g_cur[d], 1);
    g_esrc[pos] = s;
}

// ---------------- GEMM 1 + fused attention logits ----------------
// h1 = x[N,128] @ W1[128,64]. 256 thr = 16 rows x 16 col4-groups.
// Each thread: 4 cols via float4 LDS (1 LDS per 4 FFMA).
__global__ void k_gemm1(const float* __restrict__ x, const float* __restrict__ W,
                        const float* __restrict__ a_s, const float* __restrict__ a_d, int N) {
    __shared__ float sW[128 * 64];
    for (int i = threadIdx.x; i < 128 * 16; i += 256)
        *(float4*)&sW[i * 4] = __ldg(&((const float4*)W)[i]);
    __syncthreads();
    int c4   = threadIdx.x & 15;      // col group: cols c4*4..c4*4+3
    int rowl = threadIdx.x >> 4;      // 0..15
    int row  = blockIdx.x * 16 + rowl;
    if (row >= N) return;
    int head = c4 >> 2;
    float acc0 = 0.f, acc1 = 0.f, acc2 = 0.f, acc3 = 0.f;
    const float4* xr = (const float4*)(x + (size_t)row * 128);
#pragma unroll
    for (int k4 = 0; k4 < 32; k4++) {
        float4 xv = __ldg(&xr[k4]);
        float4 w0 = *(const float4*)&sW[(k4 * 4 + 0) * 64 + c4 * 4];
        float4 w1 = *(const float4*)&sW[(k4 * 4 + 1) * 64 + c4 * 4];
        float4 w2 = *(const float4*)&sW[(k4 * 4 + 2) * 64 + c4 * 4];
        float4 w3 = *(const float4*)&sW[(k4 * 4 + 3) * 64 + c4 * 4];
        acc0 = fmaf(xv.x, w0.x, acc0); acc1 = fmaf(xv.x, w0.y, acc1);
        acc2 = fmaf(xv.x, w0.z, acc2); acc3 = fmaf(xv.x, w0.w, acc3);
        acc0 = fmaf(xv.y, w1.x, acc0); acc1 = fmaf(xv.y, w1.y, acc1);
        acc2 = fmaf(xv.y, w1.z, acc2); acc3 = fmaf(xv.y, w1.w, acc3);
        acc0 = fmaf(xv.z, w2.x, acc0); acc1 = fmaf(xv.z, w2.y, acc1);
        acc2 = fmaf(xv.z, w2.z, acc2); acc3 = fmaf(xv.z, w2.w, acc3);
        acc0 = fmaf(xv.w, w3.x, acc0); acc1 = fmaf(xv.w, w3.y, acc1);
        acc2 = fmaf(xv.w, w3.z, acc2); acc3 = fmaf(xv.w, w3.w, acc3);
    }
    float4 o = { acc0, acc1, acc2, acc3 };
    *(float4*)(g_h1 + (size_t)row * 64 + c4 * 4) = o;
    // attention logits: dot with a_s/a_d over the head's 16 cols (4 lanes x 4 cols)
    const float4 as4 = *(const float4*)(a_s + c4 * 4);
    const float4 ad4 = *(const float4*)(a_d + c4 * 4);
    float s = acc0 * as4.x + acc1 * as4.y + acc2 * as4.z + acc3 * as4.w;
    float d = acc0 * ad4.x + acc1 * ad4.y + acc2 * ad4.z + acc3 * ad4.w;
    s += __shfl_xor_sync(0xffffffffu, s, 1);
    d += __shfl_xor_sync(0xffffffffu, d, 1);
    s += __shfl_xor_sync(0xffffffffu, s, 2);
    d += __shfl_xor_sync(0xffffffffu, d, 2);
    if ((c4 & 3) == 0) {
        g_als1[(size_t)row * 4 + head] = s;
        g_ald1[(size_t)row * 4 + head] = d;
    }
}

// ---------------- GEMM 2 + fused attention logits ----------------
// h2 = x2[N,64] @ W2[64,128]. 256 thr = 8 rows x 32 col4-groups.
__global__ void k_gemm2(const float* __restrict__ W,
                        const float* __restrict__ a_s, const float* __restrict__ a_d, int N) {
    __shared__ float sW[64 * 128];
    for (int i = threadIdx.x; i < 64 * 32; i += 256)
        *(float4*)&sW[i * 4] = __ldg(&((const float4*)W)[i]);
    __syncthreads();
    int c4   = threadIdx.x & 31;      // cols c4*4..c4*4+3
    int rowl = threadIdx.x >> 5;      // 0..7
    int row  = blockIdx.x * 8 + rowl;
    if (row >= N) return;
    int head = c4 >> 3;
    float acc0 = 0.f, acc1 = 0.f, acc2 = 0.f, acc3 = 0.f;
    const float4* xr = (const float4*)(g_x2 + (size_t)row * 64);
#pragma unroll
    for (int k4 = 0; k4 < 16; k4++) {
        float4 xv = xr[k4];
        float4 w0 = *(const float4*)&sW[(k4 * 4 + 0) * 128 + c4 * 4];
        float4 w1 = *(const float4*)&sW[(k4 * 4 + 1) * 128 + c4 * 4];
        float4 w2 = *(const float4*)&sW[(k4 * 4 + 2) * 128 + c4 * 4];
        float4 w3 = *(const float4*)&sW[(k4 * 4 + 3) * 128 + c4 * 4];
        acc0 = fmaf(xv.x, w0.x, acc0); acc1 = fmaf(xv.x, w0.y, acc1);
        acc2 = fmaf(xv.x, w0.z, acc2); acc3 = fmaf(xv.x, w0.w, acc3);
        acc0 = fmaf(xv.y, w1.x, acc0); acc1 = fmaf(xv.y, w1.y, acc1);
        acc2 = fmaf(xv.y, w1.z, acc2); acc3 = fmaf(xv.y, w1.w, acc3);
        acc0 = fmaf(xv.z, w2.x, acc0); acc1 = fmaf(xv.z, w2.y, acc1);
        acc2 = fmaf(xv.z, w2.z, acc2); acc3 = fmaf(xv.z, w2.w, acc3);
        acc0 = fmaf(xv.w, w3.x, acc0); acc1 = fmaf(xv.w, w3.y, acc1);
        acc2 = fmaf(xv.w, w3.z, acc2); acc3 = fmaf(xv.w, w3.w, acc3);
    }
    float4 o = { acc0, acc1, acc2, acc3 };
    *(float4*)(g_h2 + (size_t)row * 128 + c4 * 4) = o;
    const float4 as4 = *(const float4*)(a_s + c4 * 4);
    const float4 ad4 = *(const float4*)(a_d + c4 * 4);
    float s = acc0 * as4.x + acc1 * as4.y + acc2 * as4.z + acc3 * as4.w;
    float d = acc0 * ad4.x + acc1 * ad4.y + acc2 * ad4.z + acc3 * ad4.w;
    s += __shfl_xor_sync(0xffffffffu, s, 1);
    d += __shfl_xor_sync(0xffffffffu, d, 1);
    s += __shfl_xor_sync(0xffffffffu, s, 2);
    d += __shfl_xor_sync(0xffffffffu, d, 2);
    s += __shfl_xor_sync(0xffffffffu, s, 4);
    d += __shfl_xor_sync(0xffffffffu, d, 4);
    if ((c4 & 7) == 0) {
        g_als2[(size_t)row * 4 + head] = s;
        g_ald2[(size_t)row * 4 + head] = d;
    }
}

// ---------------- fused layer-1 aggregation (single pass, no max shift) ---------
__global__ void k_agg1(const float* __restrict__ b1, int N) {
    __shared__ int   sh_idx[8][32];
    __shared__ float sh_ex[8][32 * 4];
    int wid = threadIdx.x >> 5;
    int w = (blockIdx.x * blockDim.x + threadIdx.x) >> 5;
    int lane = threadIdx.x & 31;
    if (w >= N) return;
    int n = w;
    int start = g_rs[n], end = g_rs[n + 1];
    float4 ad = *(const float4*)(g_ald1 + (size_t)n * 4);

    int head = lane >> 3;
    float acc0 = 0.f, acc1 = 0.f;
    float4 den = make_float4(0.f, 0.f, 0.f, 0.f);
    for (int base = start; base < end; base += 32) {
        int i = base + lane;
        int cnt = min(32, end - base);
        int s = 0;
        float4 ex = make_float4(0.f, 0.f, 0.f, 0.f);
        if (i < end) {
            s = g_esrc[i];
            float4 a = *(const float4*)(g_als1 + (size_t)s * 4);
            ex.x = __expf(lrelu(a.x + ad.x));
            ex.y = __expf(lrelu(a.y + ad.y));
            ex.z = __expf(lrelu(a.z + ad.z));
            ex.w = __expf(lrelu(a.w + ad.w));
            den.x += ex.x; den.y += ex.y; den.z += ex.z; den.w += ex.w;
        }
        sh_idx[wid][lane] = s;
        *(float4*)&sh_ex[wid][lane * 4] = ex;
        __syncwarp();
        if (cnt == 32) {
#pragma unroll 8
            for (int j = 0; j < 32; j++) {
                int   sj  = sh_idx[wid][j];
                float exm = sh_ex[wid][j * 4 + head];
                float2 hv = *(const float2*)(g_h1 + (size_t)sj * 64 + lane * 2);
                acc0 = fmaf(exm, hv.x, acc0);
                acc1 = fmaf(exm, hv.y, acc1);
            }
        } else {
            for (int j = 0; j < cnt; j++) {
                int   sj  = sh_idx[wid][j];
                float exm = sh_ex[wid][j * 4 + head];
                float2 hv = *(const float2*)(g_h1 + (size_t)sj * 64 + lane * 2);
                acc0 = fmaf(exm, hv.x, acc0);
                acc1 = fmaf(exm, hv.y, acc1);
            }
        }
        __syncwarp();
    }
#pragma unroll
    for (int o = 16; o; o >>= 1) {
        den.x += __shfl_xor_sync(0xffffffffu, den.x, o);
        den.y += __shfl_xor_sync(0xffffffffu, den.y, o);
        den.z += __shfl_xor_sync(0xffffffffu, den.z, o);
        den.w += __shfl_xor_sync(0xffffffffu, den.w, o);
    }
    float dh = (head == 0) ? den.x : ((head == 1) ? den.y : ((head == 2) ? den.z : den.w));
    float inv = 1.f / (dh + 1e-16f);
    float2 o2;
    o2.x = fmaxf(acc0 * inv + b1[lane * 2], 0.f);
    o2.y = fmaxf(acc1 * inv + b1[lane * 2 + 1], 0.f);
    *(float2*)(g_x2 + (size_t)n * 64 + lane * 2) = o2;
}

// ---------------- fused layer-2 aggregation + pooled sums (single pass) ---------
__global__ void k_agg2(const float* __restrict__ b2, const int* __restrict__ batch, int N) {
    __shared__ int   sh_idx[8][32];
    __shared__ float sh_ex[8][32 * 4];
    int wid = threadIdx.x >> 5;
    int w = (blockIdx.x * blockDim.x + threadIdx.x) >> 5;
    int lane = threadIdx.x & 31;
    if (w >= N) return;
    int n = w;
    int start = g_rs[n], end = g_rs[n + 1];
    float4 ad = *(const float4*)(g_ald2 + (size_t)n * 4);

    int head = lane >> 3;
    float acc0 = 0.f, acc1 = 0.f, acc2 = 0.f, acc3 = 0.f;
    float4 den = make_float4(0.f, 0.f, 0.f, 0.f);
    for (int base = start; base < end; base += 32) {
        int i = base + lane;
        int cnt = min(32, end - base);
        int s = 0;
        float4 ex = make_float4(0.f, 0.f, 0.f, 0.f);
        if (i < end) {
            s = g_esrc[i];
            float4 a = *(const float4*)(g_als2 + (size_t)s * 4);
            ex.x = __expf(lrelu(a.x + ad.x));
            ex.y = __expf(lrelu(a.y + ad.y));
            ex.z = __expf(lrelu(a.z + ad.z));
            ex.w = __expf(lrelu(a.w + ad.w));
            den.x += ex.x; den.y += ex.y; den.z += ex.z; den.w += ex.w;
        }
        sh_idx[wid][lane] = s;
        *(float4*)&sh_ex[wid][lane * 4] = ex;
        __syncwarp();
        if (cnt == 32) {
#pragma unroll 4
            for (int j = 0; j < 32; j++) {
                int   sj  = sh_idx[wid][j];
                float exm = sh_ex[wid][j * 4 + head];
                float4 hv = *(const float4*)(g_h2 + (size_t)sj * 128 + lane * 4);
                acc0 = fmaf(exm, hv.x, acc0);
                acc1 = fmaf(exm, hv.y, acc1);
                acc2 = fmaf(exm, hv.z, acc2);
                acc3 = fmaf(exm, hv.w, acc3);
            }
        } else {
            for (int j = 0; j < cnt; j++) {
                int   sj  = sh_idx[wid][j];
                float exm = sh_ex[wid][j * 4 + head];
                float4 hv = *(const float4*)(g_h2 + (size_t)sj * 128 + lane * 4);
                acc0 = fmaf(exm, hv.x, acc0);
                acc1 = fmaf(exm, hv.y, acc1);
                acc2 = fmaf(exm, hv.z, acc2);
                acc3 = fmaf(exm, hv.w, acc3);
            }
        }
        __syncwarp();
    }
#pragma unroll
    for (int o = 16; o; o >>= 1) {
        den.x += __shfl_xor_sync(0xffffffffu, den.x, o);
        den.y += __shfl_xor_sync(0xffffffffu, den.y, o);
        den.z += __shfl_xor_sync(0xffffffffu, den.z, o);
        den.w += __shfl_xor_sync(0xffffffffu, den.w, o);
    }
    float dh = (head == 0) ? den.x : ((head == 1) ? den.y : ((head == 2) ? den.z : den.w));
    float inv = 1.f / (dh + 1e-16f);
    const float4 bb = *(const float4*)(b2 + lane * 4);
    float o0 = fmaxf(acc0 * inv + bb.x, 0.f);
    float o1 = fmaxf(acc1 * inv + bb.y, 0.f);
    float o2 = fmaxf(acc2 * inv + bb.z, 0.f);
    float o3 = fmaxf(acc3 * inv + bb.w, 0.f);
    int g = batch[n];
    red4(g_sums + (size_t)g * 128 + lane * 4, o0, o1, o2, o3);
    if (lane == 0) atomicAdd(&g_cnt[g], 1.f);
}

// ---------------- pool divide ----------------
__global__ void k_pool(float* __restrict__ out, int G) {
    int t = blockIdx.x * blockDim.x + threadIdx.x;
    if (t >= G * 32) return;
    int g = t >> 5;
    float inv = 1.f / fmaxf(g_cnt[g], 1.f);
    float4 s = *(const float4*)(g_sums + (size_t)t * 4);
    float4 o = { s.x * inv, s.y * inv, s.z * inv, s.w * inv };
    *(float4*)(out + (size_t)t * 4) = o;
}

// ---------------- launch ----------------
extern "C" void kernel_launch(void* const* d_in, const int* in_sizes, int n_in,
                              void* d_out, int out_size) {
    const float* x     = (const float*)d_in[0];
    const int*   ei    = (const int*)d_in[1];
    const int*   batch = (const int*)d_in[3];
    const float* W1    = (const float*)d_in[4];
    const float* a_s1  = (const float*)d_in[5];
    const float* a_d1  = (const float*)d_in[6];
    const float* b1    = (const float*)d_in[7];
    const float* W2    = (const float*)d_in[8];
    const float* a_s2  = (const float*)d_in[9];
    const float* a_d2  = (const float*)d_in[10];
    const float* b2    = (const float*)d_in[11];
    float*       out   = (float*)d_out;

    int N = in_sizes[0] / 128;
    int E = in_sizes[1] / 2;
    int G = out_size / 128;
    int T = E + N;

    void *pdeg, *ps, *pc;
    cudaGetSymbolAddress(&pdeg, g_deg);
    cudaGetSymbolAddress(&ps, g_sums);
    cudaGetSymbolAddress(&pc, g_cnt);
    cudaMemsetAsync(pdeg, 0, (size_t)N * 4);
    cudaMemsetAsync(ps, 0, (size_t)G * 128 * 4);
    cudaMemsetAsync(pc, 0, (size_t)G * 4);

    int nb = (N + 255) / 256;

    // --- CSR build (dst-grouped) ---
    k_deg<<<(T + 255) / 256, 256>>>(ei, E, N);
    k_s1<<<nb, 256>>>(N);
    k_s2<<<1, 512>>>(nb);
    k_s3<<<(N + 256) / 256, 256>>>(N, T);
    k_fill<<<(T + 255) / 256, 256>>>(ei, E, N);

    // --- layer 1 ---
    k_gemm1<<<(N + 15) / 16, 256>>>(x, W1, a_s1, a_d1, N);
    k_agg1<<<(N + 7) / 8, 256>>>(b1, N);

    // --- layer 2 ---
    k_gemm2<<<(N + 7) / 8, 256>>>(W2, a_s2, a_d2, N);
    k_agg2<<<(N + 7) / 8, 256>>>(b2, batch, N);

    // --- pool ---
    k_pool<<<(G * 32 + 255) / 256, 256>>>(out, G);
}

// round 9
// speedup vs baseline: 2.8707x; 1.0730x over previous
#include <cuda_runtime.h>

// ---------------- problem constants ----------------
#define NMAX 100000
#define GMAX 2048
#define EMAXT 3301024   // E + N + margin

// ---------------- scratch (device globals; no allocation allowed) ----------------
__device__ __align__(16) float g_h1[NMAX * 64];
__device__ __align__(16) float g_als1[NMAX * 4];
__device__ __align__(16) float g_ald1[NMAX * 4];
__device__ __align__(16) float g_x2[NMAX * 64];
__device__ __align__(16) float g_als2[NMAX * 4];
__device__ __align__(16) float g_ald2[NMAX * 4];
__device__ __align__(16) float g_hagg[NMAX * 256];   // [n][head][64], alpha-weighted x2 sums
__device__ __align__(16) float g_ws2[256];           // W2 @ a_s2 per head [4][64]
__device__ __align__(16) float g_wd2[256];
__device__ __align__(16) float g_sums[GMAX * 128];
__device__ __align__(16) float g_cnt[GMAX];
// CSR
__device__ int g_deg[NMAX];
__device__ int g_rs[NMAX + 1];
__device__ int g_cur[NMAX];
__device__ int g_esrc[EMAXT];
__device__ int g_bs[512];

// ---------------- helpers ----------------
__device__ __forceinline__ float lrelu(float e) { return e > 0.f ? e : 0.2f * e; }
__device__ __forceinline__ void red4(float* p, float a, float b, float c, float d) {
    asm volatile("red.global.add.v4.f32 [%0], {%1,%2,%3,%4};"
                 :: "l"(p), "f"(a), "f"(b), "f"(c), "f"(d) : "memory");
}

// ---------------- CSR build ----------------
__global__ void k_deg(const int* __restrict__ ei, int E, int N) {
    int t = blockIdx.x * blockDim.x + threadIdx.x;
    if (t >= E + N) return;
    int d = (t < E) ? ei[(size_t)E + t] : t - E;
    atomicAdd(&g_deg[d], 1);
}

__global__ void k_s1(int N) {
    __shared__ int sh[256];
    int t = threadIdx.x;
    int i = blockIdx.x * 256 + t;
    int v = (i < N) ? g_deg[i] : 0;
    sh[t] = v;
    __syncthreads();
    for (int o = 1; o < 256; o <<= 1) {
        int add = (t >= o) ? sh[t - o] : 0;
        __syncthreads();
        sh[t] += add;
        __syncthreads();
    }
    if (i < N) g_rs[i] = sh[t] - v;
    if (t == 255) g_bs[blockIdx.x] = sh[255];
}

__global__ void k_s2(int nb) {
    __shared__ int sh[512];
    int t = threadIdx.x;
    int v = (t < nb) ? g_bs[t] : 0;
    sh[t] = v;
    __syncthreads();
    for (int o = 1; o < 512; o <<= 1) {
        int add = (t >= o) ? sh[t - o] : 0;
        __syncthreads();
        sh[t] += add;
        __syncthreads();
    }
    if (t < nb) g_bs[t] = sh[t] - v;
}

__global__ void k_s3(int N, int T) {
    int i = blockIdx.x * 256 + threadIdx.x;
    if (i < N) {
        int v = g_rs[i] + g_bs[blockIdx.x];
        g_rs[i] = v;
        g_cur[i] = v;
    }
    if (i == N) g_rs[N] = T;
}

__global__ void k_fill(const int* __restrict__ ei, int E, int N) {
    int t = blockIdx.x * blockDim.x + threadIdx.x;
    if (t >= E + N) return;
    int s, d;
    if (t < E) { s = ei[t]; d = ei[(size_t)E + t]; }
    else       { s = d = t - E; }
    int pos = atomicAdd(&g_cur[d], 1);
    g_esrc[pos] = s;
}

// ---------------- GEMM 1 (register-tiled 4x4) + fused attention logits --------
// h1 = x[N,128] @ W1[128,64]. Block: 64 rows x 64 cols, 256 thr = 16 tr x 16 tc.
__global__ void k_gemm1(const float* __restrict__ x, const float* __restrict__ W,
                        const float* __restrict__ a_s, const float* __restrict__ a_d, int N) {
    __shared__ float sW[128 * 64];
    __shared__ float sx[32][68];    // [k-local][row], padded
    int tid = threadIdx.x;
    for (int i = tid; i < 128 * 16; i += 256)
        *(float4*)&sW[i * 4] = __ldg(&((const float4*)W)[i]);
    int tr = tid >> 4;   // 0..15 (rows tr*4..tr*4+3)
    int tc = tid & 15;   // cols tc*4..tc*4+3
    int rowBase = blockIdx.x * 64;
    float acc[4][4] = {};
    int lr = tid >> 2;   // loader row 0..63
    int lk = tid & 3;    // loader k4 group
    for (int kc = 0; kc < 4; kc++) {
        __syncthreads();
        // stage x tile transposed: rows rowBase..+63, k = kc*32..+31
#pragma unroll
        for (int half = 0; half < 2; half++) {
            int kl = half * 16 + lk * 4;
            int grow = rowBase + lr;
            float4 v = make_float4(0.f, 0.f, 0.f, 0.f);
            if (grow < N) v = __ldg((const float4*)(x + (size_t)grow * 128 + kc * 32 + kl));
            sx[kl + 0][lr] = v.x;
            sx[kl + 1][lr] = v.y;
            sx[kl + 2][lr] = v.z;
            sx[kl + 3][lr] = v.w;
        }
        __syncthreads();
#pragma unroll
        for (int kl = 0; kl < 32; kl++) {
            int k = kc * 32 + kl;
            float4 xv = *(const float4*)&sx[kl][tr * 4];
            float4 wv = *(const float4*)&sW[k * 64 + tc * 4];
            acc[0][0] = fmaf(xv.x, wv.x, acc[0][0]); acc[0][1] = fmaf(xv.x, wv.y, acc[0][1]);
            acc[0][2] = fmaf(xv.x, wv.z, acc[0][2]); acc[0][3] = fmaf(xv.x, wv.w, acc[0][3]);
            acc[1][0] = fmaf(xv.y, wv.x, acc[1][0]); acc[1][1] = fmaf(xv.y, wv.y, acc[1][1]);
            acc[1][2] = fmaf(xv.y, wv.z, acc[1][2]); acc[1][3] = fmaf(xv.y, wv.w, acc[1][3]);
            acc[2][0] = fmaf(xv.z, wv.x, acc[2][0]); acc[2][1] = fmaf(xv.z, wv.y, acc[2][1]);
            acc[2][2] = fmaf(xv.z, wv.z, acc[2][2]); acc[2][3] = fmaf(xv.z, wv.w, acc[2][3]);
            acc[3][0] = fmaf(xv.w, wv.x, acc[3][0]); acc[3][1] = fmaf(xv.w, wv.y, acc[3][1]);
            acc[3][2] = fmaf(xv.w, wv.z, acc[3][2]); acc[3][3] = fmaf(xv.w, wv.w, acc[3][3]);
        }
    }
    // store h1
#pragma unroll
    for (int r = 0; r < 4; r++) {
        int row = rowBase + tr * 4 + r;
        if (row < N) {
            float4 o = { acc[r][0], acc[r][1], acc[r][2], acc[r][3] };
            *(float4*)(g_h1 + (size_t)row * 64 + tc * 4) = o;
        }
    }
    // attention logits: head = tc>>2; reduce over tc&3 (lane bits 1..2)
    const float4 as4 = __ldg((const float4*)(a_s + tc * 4));
    const float4 ad4 = __ldg((const float4*)(a_d + tc * 4));
    float s[4], d[4];
#pragma unroll
    for (int r = 0; r < 4; r++) {
        s[r] = acc[r][0] * as4.x + acc[r][1] * as4.y + acc[r][2] * as4.z + acc[r][3] * as4.w;
        d[r] = acc[r][0] * ad4.x + acc[r][1] * ad4.y + acc[r][2] * ad4.z + acc[r][3] * ad4.w;
    }
#pragma unroll
    for (int r = 0; r < 4; r++) {
        s[r] += __shfl_xor_sync(0xffffffffu, s[r], 1);
        d[r] += __shfl_xor_sync(0xffffffffu, d[r], 1);
        s[r] += __shfl_xor_sync(0xffffffffu, s[r], 2);
        d[r] += __shfl_xor_sync(0xffffffffu, d[r], 2);
    }
    if ((tc & 3) == 0) {
        int head = tc >> 2;
#pragma unroll
        for (int r = 0; r < 4; r++) {
            int row = rowBase + tr * 4 + r;
            if (row < N) {
                g_als1[(size_t)row * 4 + head] = s[r];
                g_ald1[(size_t)row * 4 + head] = d[r];
            }
        }
    }
}

// ---------------- fused layer-1 aggregation (single pass) ----------------
__global__ void k_agg1(const float* __restrict__ b1, int N) {
    __shared__ int   sh_idx[8][32];
    __shared__ float sh_ex[8][32 * 4];
    int wid = threadIdx.x >> 5;
    int w = (blockIdx.x * blockDim.x + threadIdx.x) >> 5;
    int lane = threadIdx.x & 31;
    if (w >= N) return;
    int n = w;
    int start = g_rs[n], end = g_rs[n + 1];
    float4 ad = *(const float4*)(g_ald1 + (size_t)n * 4);

    int head = lane >> 3;
    float acc0 = 0.f, acc1 = 0.f;
    float4 den = make_float4(0.f, 0.f, 0.f, 0.f);
    for (int base = start; base < end; base += 32) {
        int i = base + lane;
        int cnt = min(32, end - base);
        int s = 0;
        float4 ex = make_float4(0.f, 0.f, 0.f, 0.f);
        if (i < end) {
            s = g_esrc[i];
            float4 a = *(const float4*)(g_als1 + (size_t)s * 4);
            ex.x = __expf(lrelu(a.x + ad.x));
            ex.y = __expf(lrelu(a.y + ad.y));
            ex.z = __expf(lrelu(a.z + ad.z));
            ex.w = __expf(lrelu(a.w + ad.w));
            den.x += ex.x; den.y += ex.y; den.z += ex.z; den.w += ex.w;
        }
        sh_idx[wid][lane] = s;
        *(float4*)&sh_ex[wid][lane * 4] = ex;
        __syncwarp();
        if (cnt == 32) {
#pragma unroll 8
            for (int j = 0; j < 32; j++) {
                int   sj  = sh_idx[wid][j];
                float exm = sh_ex[wid][j * 4 + head];
                float2 hv = *(const float2*)(g_h1 + (size_t)sj * 64 + lane * 2);
                acc0 = fmaf(exm, hv.x, acc0);
                acc1 = fmaf(exm, hv.y, acc1);
            }
        } else {
            for (int j = 0; j < cnt; j++) {
                int   sj  = sh_idx[wid][j];
                float exm = sh_ex[wid][j * 4 + head];
                float2 hv = *(const float2*)(g_h1 + (size_t)sj * 64 + lane * 2);
                acc0 = fmaf(exm, hv.x, acc0);
                acc1 = fmaf(exm, hv.y, acc1);
            }
        }
        __syncwarp();
    }
#pragma unroll
    for (int o = 16; o; o >>= 1) {
        den.x += __shfl_xor_sync(0xffffffffu, den.x, o);
        den.y += __shfl_xor_sync(0xffffffffu, den.y, o);
        den.z += __shfl_xor_sync(0xffffffffu, den.z, o);
        den.w += __shfl_xor_sync(0xffffffffu, den.w, o);
    }
    float dh = (head == 0) ? den.x : ((head == 1) ? den.y : ((head == 2) ? den.z : den.w));
    float inv = 1.f / (dh + 1e-16f);
    float2 o2;
    o2.x = fmaxf(acc0 * inv + b1[lane * 2], 0.f);
    o2.y = fmaxf(acc1 * inv + b1[lane * 2 + 1], 0.f);
    *(float2*)(g_x2 + (size_t)n * 64 + lane * 2) = o2;
}

// ---------------- layer-2 folded attention vectors: w = W2 @ a^T per head -----
__global__ void k_wvec(const float* __restrict__ W2,
                       const float* __restrict__ a_s2, const float* __restrict__ a_d2) {
    int t = threadIdx.x;          // 256 = h*64 + k
    int h = t >> 6, k = t & 63;
    float s = 0.f, d = 0.f;
    for (int c = 0; c < 32; c++) {
        float wv = W2[k * 128 + h * 32 + c];
        s = fmaf(wv, a_s2[h * 32 + c], s);
        d = fmaf(wv, a_d2[h * 32 + c], d);
    }
    g_ws2[t] = s;
    g_wd2[t] = d;
}

// ---------------- layer-2 logits: als2[n,h] = x2[n] . ws2[h] ----------------
__global__ void k_al2(int N) {
    int t = blockIdx.x * blockDim.x + threadIdx.x;
    if (t >= N * 4) return;
    int n = t >> 2, h = t & 3;
    const float4* xr = (const float4*)(g_x2 + (size_t)n * 64);
    const float4* ws = (const float4*)(g_ws2 + h * 64);
    const float4* wd = (const float4*)(g_wd2 + h * 64);
    float s = 0.f, d = 0.f;
#pragma unroll
    for (int i = 0; i < 16; i++) {
        float4 xv = xr[i], wv = ws[i], uv = wd[i];
        s = fmaf(xv.x, wv.x, s); s = fmaf(xv.y, wv.y, s);
        s = fmaf(xv.z, wv.z, s); s = fmaf(xv.w, wv.w, s);
        d = fmaf(xv.x, uv.x, d); d = fmaf(xv.y, uv.y, d);
        d = fmaf(xv.z, uv.z, d); d = fmaf(xv.w, uv.w, d);
    }
    g_als2[t] = s;
    g_ald2[t] = d;
}

// ---------------- layer-2 aggregation in x2-space (256B/edge gather) ----------
// hagg[n][h][:] = (1/den_h) * sum_e ex_e[h] * x2[src_e][:]
__global__ void k_agg2x(int N) {
    __shared__ int   sh_idx[8][32];
    __shared__ float sh_ex[8][32 * 4];
    int wid = threadIdx.x >> 5;
    int w = (blockIdx.x * blockDim.x + threadIdx.x) >> 5;
    int lane = threadIdx.x & 31;
    if (w >= N) return;
    int n = w;
    int start = g_rs[n], end = g_rs[n + 1];
    float4 ad = *(const float4*)(g_ald2 + (size_t)n * 4);

    float a00 = 0.f, a01 = 0.f, a10 = 0.f, a11 = 0.f;
    float a20 = 0.f, a21 = 0.f, a30 = 0.f, a31 = 0.f;
    float4 den = make_float4(0.f, 0.f, 0.f, 0.f);
    for (int base = start; base < end; base += 32) {
        int i = base + lane;
        int cnt = min(32, end - base);
        int s = 0;
        float4 ex = make_float4(0.f, 0.f, 0.f, 0.f);
        if (i < end) {
            s = g_esrc[i];
            float4 a = *(const float4*)(g_als2 + (size_t)s * 4);
            ex.x = __expf(lrelu(a.x + ad.x));
            ex.y = __expf(lrelu(a.y + ad.y));
            ex.z = __expf(lrelu(a.z + ad.z));
            ex.w = __expf(lrelu(a.w + ad.w));
            den.x += ex.x; den.y += ex.y; den.z += ex.z; den.w += ex.w;
        }
        sh_idx[wid][lane] = s;
        *(float4*)&sh_ex[wid][lane * 4] = ex;
        __syncwarp();
        if (cnt == 32) {
#pragma unroll 4
            for (int j = 0; j < 32; j++) {
                int    sj = sh_idx[wid][j];
                float4 e4 = *(const float4*)&sh_ex[wid][j * 4];
                float2 xv = *(const float2*)(g_x2 + (size_t)sj * 64 + lane * 2);
                a00 = fmaf(e4.x, xv.x, a00); a01 = fmaf(e4.x, xv.y, a01);
                a10 = fmaf(e4.y, xv.x, a10); a11 = fmaf(e4.y, xv.y, a11);
                a20 = fmaf(e4.z, xv.x, a20); a21 = fmaf(e4.z, xv.y, a21);
                a30 = fmaf(e4.w, xv.x, a30); a31 = fmaf(e4.w, xv.y, a31);
            }
        } else {
            for (int j = 0; j < cnt; j++) {
                int    sj = sh_idx[wid][j];
                float4 e4 = *(const float4*)&sh_ex[wid][j * 4];
                float2 xv = *(const float2*)(g_x2 + (size_t)sj * 64 + lane * 2);
                a00 = fmaf(e4.x, xv.x, a00); a01 = fmaf(e4.x, xv.y, a01);
                a10 = fmaf(e4.y, xv.x, a10); a11 = fmaf(e4.y, xv.y, a11);
                a20 = fmaf(e4.z, xv.x, a20); a21 = fmaf(e4.z, xv.y, a21);
                a30 = fmaf(e4.w, xv.x, a30); a31 = fmaf(e4.w, xv.y, a31);
            }
        }
        __syncwarp();
    }
#pragma unroll
    for (int o = 16; o; o >>= 1) {
        den.x += __shfl_xor_sync(0xffffffffu, den.x, o);
        den.y += __shfl_xor_sync(0xffffffffu, den.y, o);
        den.z += __shfl_xor_sync(0xffffffffu, den.z, o);
        den.w += __shfl_xor_sync(0xffffffffu, den.w, o);
    }
    float i0 = 1.f / (den.x + 1e-16f);
    float i1 = 1.f / (den.y + 1e-16f);
    float i2 = 1.f / (den.z + 1e-16f);
    float i3 = 1.f / (den.w + 1e-16f);
    float* hg = g_hagg + (size_t)n * 256;
    float2 v;
    v.x = a00 * i0; v.y = a01 * i0; *(float2*)(hg +   0 + lane * 2) = v;
    v.x = a10 * i1; v.y = a11 * i1; *(float2*)(hg +  64 + lane * 2) = v;
    v.x = a20 * i2; v.y = a21 * i2; *(float2*)(hg + 128 + lane * 2) = v;
    v.x = a30 * i3; v.y = a31 * i3; *(float2*)(hg + 192 + lane * 2) = v;
}

// ---------------- post-agg GEMM2 + bias + relu + pooled sums ----------------
// out[n, h*32+c] = relu(hagg[n][h] . W2[:, h*32+c] + b2[...]), red4 into g_sums
__global__ void k_out(const float* __restrict__ W2, const float* __restrict__ b2,
                      const int* __restrict__ batch, int N) {
    __shared__ float sW[64 * 128];
    for (int i = threadIdx.x; i < 64 * 32; i += 256)
        *(float4*)&sW[i * 4] = __ldg(&((const float4*)W2)[i]);
    __syncthreads();
    int c4   = threadIdx.x & 31;   // cols c4*4..+3
    int rowl = threadIdx.x >> 5;
    int row  = blockIdx.x * 8 + rowl;
    if (row >= N) return;
    int head = c4 >> 3;
    const float4* hr = (const float4*)(g_hagg + (size_t)row * 256 + head * 64);
    float acc0 = 0.f, acc1 = 0.f, acc2 = 0.f, acc3 = 0.f;
#pragma unroll
    for (int k4 = 0; k4 < 16; k4++) {
        float4 xv = hr[k4];
        float4 w0 = *(const float4*)&sW[(k4 * 4 + 0) * 128 + c4 * 4];
        float4 w1 = *(const float4*)&sW[(k4 * 4 + 1) * 128 + c4 * 4];
        float4 w2 = *(const float4*)&sW[(k4 * 4 + 2) * 128 + c4 * 4];
        float4 w3 = *(const float4*)&sW[(k4 * 4 + 3) * 128 + c4 * 4];
        acc0 = fmaf(xv.x, w0.x, acc0); acc1 = fmaf(xv.x, w0.y, acc1);
        acc2 = fmaf(xv.x, w0.z, acc2); acc3 = fmaf(xv.x, w0.w, acc3);
        acc0 = fmaf(xv.y, w1.x, acc0); acc1 = fmaf(xv.y, w1.y, acc1);
        acc2 = fmaf(xv.y, w1.z, acc2); acc3 = fmaf(xv.y, w1.w, acc3);
        acc0 = fmaf(xv.z, w2.x, acc0); acc1 = fmaf(xv.z, w2.y, acc1);
        acc2 = fmaf(xv.z, w2.z, acc2); acc3 = fmaf(xv.z, w2.w, acc3);
        acc0 = fmaf(xv.w, w3.x, acc0); acc1 = fmaf(xv.w, w3.y, acc1);
        acc2 = fmaf(xv.w, w3.z, acc2); acc3 = fmaf(xv.w, w3.w, acc3);
    }
    const float4 bb = __ldg((const float4*)(b2 + c4 * 4));
    float o0 = fmaxf(acc0 + bb.x, 0.f);
    float o1 = fmaxf(acc1 + bb.y, 0.f);
    float o2 = fmaxf(acc2 + bb.z, 0.f);
    float o3 = fmaxf(acc3 + bb.w, 0.f);
    int g = batch[row];
    red4(g_sums + (size_t)g * 128 + c4 * 4, o0, o1, o2, o3);
    if (c4 == 0) atomicAdd(&g_cnt[g], 1.f);
}

// ---------------- pool divide ----------------
__global__ void k_pool(float* __restrict__ out, int G) {
    int t = blockIdx.x * blockDim.x + threadIdx.x;
    if (t >= G * 32) return;
    int g = t >> 5;
    float inv = 1.f / fmaxf(g_cnt[g], 1.f);
    float4 s = *(const float4*)(g_sums + (size_t)t * 4);
    float4 o = { s.x * inv, s.y * inv, s.z * inv, s.w * inv };
    *(float4*)(out + (size_t)t * 4) = o;
}

// ---------------- launch ----------------
extern "C" void kernel_launch(void* const* d_in, const int* in_sizes, int n_in,
                              void* d_out, int out_size) {
    const float* x     = (const float*)d_in[0];
    const int*   ei    = (const int*)d_in[1];
    const int*   batch = (const int*)d_in[3];
    const float* W1    = (const float*)d_in[4];
    const float* a_s1  = (const float*)d_in[5];
    const float* a_d1  = (const float*)d_in[6];
    const float* b1    = (const float*)d_in[7];
    const float* W2    = (const float*)d_in[8];
    const float* a_s2  = (const float*)d_in[9];
    const float* a_d2  = (const float*)d_in[10];
    const float* b2    = (const float*)d_in[11];
    float*       out   = (float*)d_out;

    int N = in_sizes[0] / 128;
    int E = in_sizes[1] / 2;
    int G = out_size / 128;
    int T = E + N;

    void *pdeg, *ps, *pc;
    cudaGetSymbolAddress(&pdeg, g_deg);
    cudaGetSymbolAddress(&ps, g_sums);
    cudaGetSymbolAddress(&pc, g_cnt);
    cudaMemsetAsync(pdeg, 0, (size_t)N * 4);
    cudaMemsetAsync(ps, 0, (size_t)G * 128 * 4);
    cudaMemsetAsync(pc, 0, (size_t)G * 4);

    int nb = (N + 255) / 256;

    // --- CSR build (dst-grouped) ---
    k_deg<<<(T + 255) / 256, 256>>>(ei, E, N);
    k_s1<<<nb, 256>>>(N);
    k_s2<<<1, 512>>>(nb);
    k_s3<<<(N + 256) / 256, 256>>>(N, T);
    k_fill<<<(T + 255) / 256, 256>>>(ei, E, N);

    // --- fold W2 @ a2 (independent of layer 1; launch early) ---
    k_wvec<<<1, 256>>>(W2, a_s2, a_d2);

    // --- layer 1 ---
    k_gemm1<<<(N + 63) / 64, 256>>>(x, W1, a_s1, a_d1, N);
    k_agg1<<<(N + 7) / 8, 256>>>(b1, N);

    // --- layer 2 (aggregate in x2 space, GEMM after) ---
    k_al2<<<(N * 4 + 255) / 256, 256>>>(N);
    k_agg2x<<<(N + 7) / 8, 256>>>(N);
    k_out<<<(N + 7) / 8, 256>>>(W2, b2, batch, N);

    // --- pool ---
    k_pool<<<(G * 32 + 255) / 256, 256>>>(out, G);
}

// round 11
// speedup vs baseline: 3.0097x; 1.0484x over previous
#include <cuda_runtime.h>

// ---------------- problem constants ----------------
#define NMAX 100000
#define GMAX 2048
#define EMAXT 3301024   // E + N + margin

// ---------------- scratch (device globals; no allocation allowed) ----------------
__device__ __align__(16) float g_h1[NMAX * 64];
__device__ __align__(16) float g_als1[NMAX * 4];
__device__ __align__(16) float g_ald1[NMAX * 4];
__device__ __align__(16) float g_x2[NMAX * 64];
__device__ __align__(16) float g_als2[NMAX * 4];
__device__ __align__(16) float g_ald2[NMAX * 4];
__device__ __align__(16) float g_hagg[NMAX * 256];   // [n][head][64], alpha-weighted x2 sums
__device__ __align__(16) float g_ws2[256];           // W2 @ a_s2 per head [4][64]
__device__ __align__(16) float g_wd2[256];
__device__ __align__(16) float g_sums[GMAX * 128];
__device__ __align__(16) float g_cnt[GMAX];
// CSR
__device__ int g_deg[NMAX];
__device__ int g_rs[NMAX + 1];
__device__ int g_cur[NMAX];
__device__ int g_esrc[EMAXT];
__device__ int g_bs[512];

// ---------------- helpers ----------------
__device__ __forceinline__ float lrelu(float e) { return e > 0.f ? e : 0.2f * e; }
__device__ __forceinline__ void red4(float* p, float a, float b, float c, float d) {
    asm volatile("red.global.add.v4.f32 [%0], {%1,%2,%3,%4};"
                 :: "l"(p), "f"(a), "f"(b), "f"(c), "f"(d) : "memory");
}

// ---------------- CSR build ----------------
__global__ void k_deg(const int* __restrict__ ei, int E, int N) {
    int t = blockIdx.x * blockDim.x + threadIdx.x;
    if (t >= E + N) return;
    int d = (t < E) ? ei[(size_t)E + t] : t - E;
    atomicAdd(&g_deg[d], 1);
}

__global__ void k_s1(int N) {
    __shared__ int sh[256];
    int t = threadIdx.x;
    int i = blockIdx.x * 256 + t;
    int v = (i < N) ? g_deg[i] : 0;
    sh[t] = v;
    __syncthreads();
    for (int o = 1; o < 256; o <<= 1) {
        int add = (t >= o) ? sh[t - o] : 0;
        __syncthreads();
        sh[t] += add;
        __syncthreads();
    }
    if (i < N) g_rs[i] = sh[t] - v;
    if (t == 255) g_bs[blockIdx.x] = sh[255];
}

__global__ void k_s2(int nb) {
    __shared__ int sh[512];
    int t = threadIdx.x;
    int v = (t < nb) ? g_bs[t] : 0;
    sh[t] = v;
    __syncthreads();
    for (int o = 1; o < 512; o <<= 1) {
        int add = (t >= o) ? sh[t - o] : 0;
        __syncthreads();
        sh[t] += add;
        __syncthreads();
    }
    if (t < nb) g_bs[t] = sh[t] - v;
}

__global__ void k_s3(int N, int T) {
    int i = blockIdx.x * 256 + threadIdx.x;
    if (i < N) {
        int v = g_rs[i] + g_bs[blockIdx.x];
        g_rs[i] = v;
        g_cur[i] = v;
    }
    if (i == N) g_rs[N] = T;
}

__global__ void k_fill(const int* __restrict__ ei, int E, int N) {
    int t = blockIdx.x * blockDim.x + threadIdx.x;
    if (t >= E + N) return;
    int s, d;
    if (t < E) { s = ei[t]; d = ei[(size_t)E + t]; }
    else       { s = d = t - E; }
    int pos = atomicAdd(&g_cur[d], 1);
    g_esrc[pos] = s;
}

// ---------------- GEMM 1 (register-tiled 4x4) + fused attention logits --------
__global__ void k_gemm1(const float* __restrict__ x, const float* __restrict__ W,
                        const float* __restrict__ a_s, const float* __restrict__ a_d, int N) {
    __shared__ float sW[128 * 64];
    __shared__ float sx[32][68];    // [k-local][row], padded
    int tid = threadIdx.x;
    for (int i = tid; i < 128 * 16; i += 256)
        *(float4*)&sW[i * 4] = __ldg(&((const float4*)W)[i]);
    int tr = tid >> 4;   // 0..15
    int tc = tid & 15;
    int rowBase = blockIdx.x * 64;
    float acc[4][4] = {};
    int lr = tid >> 2;
    int lk = tid & 3;
    for (int kc = 0; kc < 4; kc++) {
        __syncthreads();
#pragma unroll
        for (int half = 0; half < 2; half++) {
            int kl = half * 16 + lk * 4;
            int grow = rowBase + lr;
            float4 v = make_float4(0.f, 0.f, 0.f, 0.f);
            if (grow < N) v = __ldg((const float4*)(x + (size_t)grow * 128 + kc * 32 + kl));
            sx[kl + 0][lr] = v.x;
            sx[kl + 1][lr] = v.y;
            sx[kl + 2][lr] = v.z;
            sx[kl + 3][lr] = v.w;
        }
        __syncthreads();
#pragma unroll
        for (int kl = 0; kl < 32; kl++) {
            int k = kc * 32 + kl;
            float4 xv = *(const float4*)&sx[kl][tr * 4];
            float4 wv = *(const float4*)&sW[k * 64 + tc * 4];
            acc[0][0] = fmaf(xv.x, wv.x, acc[0][0]); acc[0][1] = fmaf(xv.x, wv.y, acc[0][1]);
            acc[0][2] = fmaf(xv.x, wv.z, acc[0][2]); acc[0][3] = fmaf(xv.x, wv.w, acc[0][3]);
            acc[1][0] = fmaf(xv.y, wv.x, acc[1][0]); acc[1][1] = fmaf(xv.y, wv.y, acc[1][1]);
            acc[1][2] = fmaf(xv.y, wv.z, acc[1][2]); acc[1][3] = fmaf(xv.y, wv.w, acc[1][3]);
            acc[2][0] = fmaf(xv.z, wv.x, acc[2][0]); acc[2][1] = fmaf(xv.z, wv.y, acc[2][1]);
            acc[2][2] = fmaf(xv.z, wv.z, acc[2][2]); acc[2][3] = fmaf(xv.z, wv.w, acc[2][3]);
            acc[3][0] = fmaf(xv.w, wv.x, acc[3][0]); acc[3][1] = fmaf(xv.w, wv.y, acc[3][1]);
            acc[3][2] = fmaf(xv.w, wv.z, acc[3][2]); acc[3][3] = fmaf(xv.w, wv.w, acc[3][3]);
        }
    }
#pragma unroll
    for (int r = 0; r < 4; r++) {
        int row = rowBase + tr * 4 + r;
        if (row < N) {
            float4 o = { acc[r][0], acc[r][1], acc[r][2], acc[r][3] };
            *(float4*)(g_h1 + (size_t)row * 64 + tc * 4) = o;
        }
    }
    const float4 as4 = __ldg((const float4*)(a_s + tc * 4));
    const float4 ad4 = __ldg((const float4*)(a_d + tc * 4));
    float s[4], d[4];
#pragma unroll
    for (int r = 0; r < 4; r++) {
        s[r] = acc[r][0] * as4.x + acc[r][1] * as4.y + acc[r][2] * as4.z + acc[r][3] * as4.w;
        d[r] = acc[r][0] * ad4.x + acc[r][1] * ad4.y + acc[r][2] * ad4.z + acc[r][3] * ad4.w;
    }
#pragma unroll
    for (int r = 0; r < 4; r++) {
        s[r] += __shfl_xor_sync(0xffffffffu, s[r], 1);
        d[r] += __shfl_xor_sync(0xffffffffu, d[r], 1);
        s[r] += __shfl_xor_sync(0xffffffffu, s[r], 2);
        d[r] += __shfl_xor_sync(0xffffffffu, d[r], 2);
    }
    if ((tc & 3) == 0) {
        int head = tc >> 2;
#pragma unroll
        for (int r = 0; r < 4; r++) {
            int row = rowBase + tr * 4 + r;
            if (row < N) {
                g_als1[(size_t)row * 4 + head] = s[r];
                g_ald1[(size_t)row * 4 + head] = d[r];
            }
        }
    }
}

// ---------------- layer-2 folded attention vectors: w = W2 @ a^T per head -----
__global__ void k_wvec(const float* __restrict__ W2,
                       const float* __restrict__ a_s2, const float* __restrict__ a_d2) {
    int t = threadIdx.x;          // 256 = h*64 + k
    int h = t >> 6, k = t & 63;
    float s = 0.f, d = 0.f;
    for (int c = 0; c < 32; c++) {
        float wv = W2[k * 128 + h * 32 + c];
        s = fmaf(wv, a_s2[h * 32 + c], s);
        d = fmaf(wv, a_d2[h * 32 + c], d);
    }
    g_ws2[t] = s;
    g_wd2[t] = d;
}

// ---------------- fused layer-1 aggregation + layer-2 logits ----------------
__global__ void k_agg1(const float* __restrict__ b1, int N) {
    __shared__ int   sh_idx[8][32];
    __shared__ float sh_ex[8][32 * 4];
    int wid = threadIdx.x >> 5;
    int w = (blockIdx.x * blockDim.x + threadIdx.x) >> 5;
    int lane = threadIdx.x & 31;
    if (w >= N) return;
    int n = w;
    int start = g_rs[n], end = g_rs[n + 1];
    float4 ad = *(const float4*)(g_ald1 + (size_t)n * 4);

    int head = lane >> 3;
    float acc0 = 0.f, acc1 = 0.f;
    float4 den = make_float4(0.f, 0.f, 0.f, 0.f);
    for (int base = start; base < end; base += 32) {
        int i = base + lane;
        int cnt = min(32, end - base);
        int s = 0;
        float4 ex = make_float4(0.f, 0.f, 0.f, 0.f);
        if (i < end) {
            s = g_esrc[i];
            float4 a = *(const float4*)(g_als1 + (size_t)s * 4);
            ex.x = __expf(lrelu(a.x + ad.x));
            ex.y = __expf(lrelu(a.y + ad.y));
            ex.z = __expf(lrelu(a.z + ad.z));
            ex.w = __expf(lrelu(a.w + ad.w));
            den.x += ex.x; den.y += ex.y; den.z += ex.z; den.w += ex.w;
        }
        sh_idx[wid][lane] = s;
        *(float4*)&sh_ex[wid][lane * 4] = ex;
        __syncwarp();
        if (cnt == 32) {
#pragma unroll 8
            for (int j = 0; j < 32; j++) {
                int   sj  = sh_idx[wid][j];
                float exm = sh_ex[wid][j * 4 + head];
                float2 hv = *(const float2*)(g_h1 + (size_t)sj * 64 + lane * 2);
                acc0 = fmaf(exm, hv.x, acc0);
                acc1 = fmaf(exm, hv.y, acc1);
            }
        } else {
            for (int j = 0; j < cnt; j++) {
                int   sj  = sh_idx[wid][j];
                float exm = sh_ex[wid][j * 4 + head];
                float2 hv = *(const float2*)(g_h1 + (size_t)sj * 64 + lane * 2);
                acc0 = fmaf(exm, hv.x, acc0);
                acc1 = fmaf(exm, hv.y, acc1);
            }
        }
        __syncwarp();
    }
#pragma unroll
    for (int o = 16; o; o >>= 1) {
        den.x += __shfl_xor_sync(0xffffffffu, den.x, o);
        den.y += __shfl_xor_sync(0xffffffffu, den.y, o);
        den.z += __shfl_xor_sync(0xffffffffu, den.z, o);
        den.w += __shfl_xor_sync(0xffffffffu, den.w, o);
    }
    float dh = (head == 0) ? den.x : ((head == 1) ? den.y : ((head == 2) ? den.z : den.w));
    float inv = 1.f / (dh + 1e-16f);
    float2 o2;
    o2.x = fmaxf(acc0 * inv + b1[lane * 2], 0.f);
    o2.y = fmaxf(acc1 * inv + b1[lane * 2 + 1], 0.f);
    *(float2*)(g_x2 + (size_t)n * 64 + lane * 2) = o2;

    // fused layer-2 logits: als2[n,h] = x2[n] . ws2[h] (x2 row live in registers)
#pragma unroll
    for (int h = 0; h < 4; h++) {
        float2 ws = *(const float2*)(g_ws2 + h * 64 + lane * 2);
        float2 wd = *(const float2*)(g_wd2 + h * 64 + lane * 2);
        float sv = o2.x * ws.x + o2.y * ws.y;
        float dv = o2.x * wd.x + o2.y * wd.y;
#pragma unroll
        for (int o = 16; o; o >>= 1) {
            sv += __shfl_xor_sync(0xffffffffu, sv, o);
            dv += __shfl_xor_sync(0xffffffffu, dv, o);
        }
        if (lane == 0) {
            g_als2[(size_t)n * 4 + h] = sv;
            g_ald2[(size_t)n * 4 + h] = dv;
        }
    }
}

// ---------------- layer-2 aggregation in x2-space (256B/edge gather) ----------
__global__ void k_agg2x(int N) {
    __shared__ int   sh_idx[8][32];
    __shared__ float sh_ex[8][32 * 4];
    int wid = threadIdx.x >> 5;
    int w = (blockIdx.x * blockDim.x + threadIdx.x) >> 5;
    int lane = threadIdx.x & 31;
    if (w >= N) return;
    int n = w;
    int start = g_rs[n], end = g_rs[n + 1];
    float4 ad = *(const float4*)(g_ald2 + (size_t)n * 4);

    float a00 = 0.f, a01 = 0.f, a10 = 0.f, a11 = 0.f;
    float a20 = 0.f, a21 = 0.f, a30 = 0.f, a31 = 0.f;
    float4 den = make_float4(0.f, 0.f, 0.f, 0.f);
    for (int base = start; base < end; base += 32) {
        int i = base + lane;
        int cnt = min(32, end - base);
        int s = 0;
        float4 ex = make_float4(0.f, 0.f, 0.f, 0.f);
        if (i < end) {
            s = g_esrc[i];
            float4 a = *(const float4*)(g_als2 + (size_t)s * 4);
            ex.x = __expf(lrelu(a.x + ad.x));
            ex.y = __expf(lrelu(a.y + ad.y));
            ex.z = __expf(lrelu(a.z + ad.z));
            ex.w = __expf(lrelu(a.w + ad.w));
            den.x += ex.x; den.y += ex.y; den.z += ex.z; den.w += ex.w;
        }
        sh_idx[wid][lane] = s;
        *(float4*)&sh_ex[wid][lane * 4] = ex;
        __syncwarp();
        if (cnt == 32) {
#pragma unroll 4
            for (int j = 0; j < 32; j++) {
                int    sj = sh_idx[wid][j];
                float4 e4 = *(const float4*)&sh_ex[wid][j * 4];
                float2 xv = *(const float2*)(g_x2 + (size_t)sj * 64 + lane * 2);
                a00 = fmaf(e4.x, xv.x, a00); a01 = fmaf(e4.x, xv.y, a01);
                a10 = fmaf(e4.y, xv.x, a10); a11 = fmaf(e4.y, xv.y, a11);
                a20 = fmaf(e4.z, xv.x, a20); a21 = fmaf(e4.z, xv.y, a21);
                a30 = fmaf(e4.w, xv.x, a30); a31 = fmaf(e4.w, xv.y, a31);
            }
        } else {
            for (int j = 0; j < cnt; j++) {
                int    sj = sh_idx[wid][j];
                float4 e4 = *(const float4*)&sh_ex[wid][j * 4];
                float2 xv = *(const float2*)(g_x2 + (size_t)sj * 64 + lane * 2);
                a00 = fmaf(e4.x, xv.x, a00); a01 = fmaf(e4.x, xv.y, a01);
                a10 = fmaf(e4.y, xv.x, a10); a11 = fmaf(e4.y, xv.y, a11);
                a20 = fmaf(e4.z, xv.x, a20); a21 = fmaf(e4.z, xv.y, a21);
                a30 = fmaf(e4.w, xv.x, a30); a31 = fmaf(e4.w, xv.y, a31);
            }
        }
        __syncwarp();
    }
#pragma unroll
    for (int o = 16; o; o >>= 1) {
        den.x += __shfl_xor_sync(0xffffffffu, den.x, o);
        den.y += __shfl_xor_sync(0xffffffffu, den.y, o);
        den.z += __shfl_xor_sync(0xffffffffu, den.z, o);
        den.w += __shfl_xor_sync(0xffffffffu, den.w, o);
    }
    float i0 = 1.f / (den.x + 1e-16f);
    float i1 = 1.f / (den.y + 1e-16f);
    float i2 = 1.f / (den.z + 1e-16f);
    float i3 = 1.f / (den.w + 1e-16f);
    float* hg = g_hagg + (size_t)n * 256;
    float2 v;
    v.x = a00 * i0; v.y = a01 * i0; *(float2*)(hg +   0 + lane * 2) = v;
    v.x = a10 * i1; v.y = a11 * i1; *(float2*)(hg +  64 + lane * 2) = v;
    v.x = a20 * i2; v.y = a21 * i2; *(float2*)(hg + 128 + lane * 2) = v;
    v.x = a30 * i3; v.y = a31 * i3; *(float2*)(hg + 192 + lane * 2) = v;
}

// ---------------- post-agg GEMM2 + bias + relu + pooled sums ----------------
// 64 rows per block: sW loaded once, 8 row-batches
__global__ void k_out(const float* __restrict__ W2, const float* __restrict__ b2,
                      const int* __restrict__ batch, int N) {
    __shared__ float sW[64 * 128];
    for (int i = threadIdx.x; i < 64 * 32; i += 256)
        *(float4*)&sW[i * 4] = __ldg(&((const float4*)W2)[i]);
    __syncthreads();
    int c4   = threadIdx.x & 31;   // cols c4*4..+3
    int rowl = threadIdx.x >> 5;   // 0..7
    int head = c4 >> 3;
    const float4 bb = __ldg((const float4*)(b2 + c4 * 4));
    int rowBase = blockIdx.x * 64;
#pragma unroll 1
    for (int rb = 0; rb < 8; rb++) {
        int row = rowBase + rb * 8 + rowl;
        if (row >= N) break;
        const float4* hr = (const float4*)(g_hagg + (size_t)row * 256 + head * 64);
        float acc0 = 0.f, acc1 = 0.f, acc2 = 0.f, acc3 = 0.f;
#pragma unroll
        for (int k4 = 0; k4 < 16; k4++) {
            float4 xv = hr[k4];
            float4 w0 = *(const float4*)&sW[(k4 * 4 + 0) * 128 + c4 * 4];
            float4 w1 = *(const float4*)&sW[(k4 * 4 + 1) * 128 + c4 * 4];
            float4 w2 = *(const float4*)&sW[(k4 * 4 + 2) * 128 + c4 * 4];
            float4 w3 = *(const float4*)&sW[(k4 * 4 + 3) * 128 + c4 * 4];
            acc0 = fmaf(xv.x, w0.x, acc0); acc1 = fmaf(xv.x, w0.y, acc1);
            acc2 = fmaf(xv.x, w0.z, acc2); acc3 = fmaf(xv.x, w0.w, acc3);
            acc0 = fmaf(xv.y, w1.x, acc0); acc1 = fmaf(xv.y, w1.y, acc1);
            acc2 = fmaf(xv.y, w1.z, acc2); acc3 = fmaf(xv.y, w1.w, acc3);
            acc0 = fmaf(xv.z, w2.x, acc0); acc1 = fmaf(xv.z, w2.y, acc1);
            acc2 = fmaf(xv.z, w2.z, acc2); acc3 = fmaf(xv.z, w2.w, acc3);
            acc0 = fmaf(xv.w, w3.x, acc0); acc1 = fmaf(xv.w, w3.y, acc1);
            acc2 = fmaf(xv.w, w3.z, acc2); acc3 = fmaf(xv.w, w3.w, acc3);
        }
        float o0 = fmaxf(acc0 + bb.x, 0.f);
        float o1 = fmaxf(acc1 + bb.y, 0.f);
        float o2 = fmaxf(acc2 + bb.z, 0.f);
        float o3 = fmaxf(acc3 + bb.w, 0.f);
        int g = batch[row];
        red4(g_sums + (size_t)g * 128 + c4 * 4, o0, o1, o2, o3);
        if (c4 == 0) atomicAdd(&g_cnt[g], 1.f);
    }
}

// ---------------- pool divide ----------------
__global__ void k_pool(float* __restrict__ out, int G) {
    int t = blockIdx.x * blockDim.x + threadIdx.x;
    if (t >= G * 32) return;
    int g = t >> 5;
    float inv = 1.f / fmaxf(g_cnt[g], 1.f);
    float4 s = *(const float4*)(g_sums + (size_t)t * 4);
    float4 o = { s.x * inv, s.y * inv, s.z * inv, s.w * inv };
    *(float4*)(out + (size_t)t * 4) = o;
}

// ---------------- launch ----------------
extern "C" void kernel_launch(void* const* d_in, const int* in_sizes, int n_in,
                              void* d_out, int out_size) {
    const float* x     = (const float*)d_in[0];
    const int*   ei    = (const int*)d_in[1];
    const int*   batch = (const int*)d_in[3];
    const float* W1    = (const float*)d_in[4];
    const float* a_s1  = (const float*)d_in[5];
    const float* a_d1  = (const float*)d_in[6];
    const float* b1    = (const float*)d_in[7];
    const float* W2    = (const float*)d_in[8];
    const float* a_s2  = (const float*)d_in[9];
    const float* a_d2  = (const float*)d_in[10];
    const float* b2    = (const float*)d_in[11];
    float*       out   = (float*)d_out;

    int N = in_sizes[0] / 128;
    int E = in_sizes[1] / 2;
    int G = out_size / 128;
    int T = E + N;

    void *pdeg, *ps, *pc;
    cudaGetSymbolAddress(&pdeg, g_deg);
    cudaGetSymbolAddress(&ps, g_sums);
    cudaGetSymbolAddress(&pc, g_cnt);
    cudaMemsetAsync(pdeg, 0, (size_t)N * 4);
    cudaMemsetAsync(ps, 0, (size_t)G * 128 * 4);
    cudaMemsetAsync(pc, 0, (size_t)G * 4);

    int nb = (N + 255) / 256;

    // --- CSR build (dst-grouped) ---
    k_deg<<<(T + 255) / 256, 256>>>(ei, E, N);
    k_s1<<<nb, 256>>>(N);
    k_s2<<<1, 512>>>(nb);
    k_s3<<<(N + 256) / 256, 256>>>(N, T);
    k_fill<<<(T + 255) / 256, 256>>>(ei, E, N);

    // --- fold W2 @ a2 (needed by k_agg1's fused epilogue) ---
    k_wvec<<<1, 256>>>(W2, a_s2, a_d2);

    // --- layer 1 (+ fused layer-2 logits) ---
    k_gemm1<<<(N + 63) / 64, 256>>>(x, W1, a_s1, a_d1, N);
    k_agg1<<<(N + 7) / 8, 256>>>(b1, N);

    // --- layer 2 ---
    k_agg2x<<<(N + 7) / 8, 256>>>(N);
    k_out<<<(N + 63) / 64, 256>>>(W2, b2, batch, N);

    // --- pool ---
    k_pool<<<(G * 32 + 255) / 256, 256>>>(out, G);
}

// round 13
// speedup vs baseline: 3.2115x; 1.0670x over previous
#include <cuda_runtime.h>
#include <cuda_fp16.h>

// ---------------- problem constants ----------------
#define NMAX 100000
#define GMAX 2048
#define EMAXT 3301024   // E + N + margin

// ---------------- scratch ----------------
__device__ __align__(16) __half g_h1h[NMAX * 64];     // h1 in fp16
__device__ __align__(16) float  g_als1[NMAX * 4];
__device__ __align__(16) float  g_ald1[NMAX * 4];
__device__ __align__(16) __half g_x2h[NMAX * 64];     // x2 in fp16
__device__ __align__(16) float  g_als2[NMAX * 4];
__device__ __align__(16) float  g_ald2[NMAX * 4];
__device__ __align__(16) float  g_hagg[NMAX * 256];   // [n][head][64]
__device__ __align__(16) float  g_ws2[256];
__device__ __align__(16) float  g_wd2[256];
__device__ __align__(16) float  g_sums[GMAX * 128];
__device__ __align__(16) float  g_cnt[GMAX];
// CSR
__device__ int g_deg[NMAX];
__device__ int g_rs[NMAX + 1];
__device__ int g_cur[NMAX];
__device__ int g_esrc[EMAXT];
__device__ int g_bs[512];

// ---------------- helpers ----------------
__device__ __forceinline__ float lrelu(float e) { return e > 0.f ? e : 0.2f * e; }
__device__ __forceinline__ void red4(float* p, float a, float b, float c, float d) {
    asm volatile("red.global.add.v4.f32 [%0], {%1,%2,%3,%4};"
                 :: "l"(p), "f"(a), "f"(b), "f"(c), "f"(d) : "memory");
}

// ---------------- CSR build ----------------
__global__ void k_deg(const int* __restrict__ ei, int E) {
    int t = blockIdx.x * blockDim.x + threadIdx.x;
    if (t >= E) return;
    atomicAdd(&g_deg[ei[(size_t)E + t]], 1);
}

__global__ void k_s1(int N) {
    __shared__ int sh[256];
    int t = threadIdx.x;
    int i = blockIdx.x * 256 + t;
    int v = (i < N) ? g_deg[i] + 1 : 0;   // +1 self loop
    sh[t] = v;
    __syncthreads();
    for (int o = 1; o < 256; o <<= 1) {
        int add = (t >= o) ? sh[t - o] : 0;
        __syncthreads();
        sh[t] += add;
        __syncthreads();
    }
    if (i < N) g_rs[i] = sh[t] - v;
    if (t == 255) g_bs[blockIdx.x] = sh[255];
}

__global__ void k_s2(int nb) {
    __shared__ int sh[512];
    int t = threadIdx.x;
    int v = (t < nb) ? g_bs[t] : 0;
    sh[t] = v;
    __syncthreads();
    for (int o = 1; o < 512; o <<= 1) {
        int add = (t >= o) ? sh[t - o] : 0;
        __syncthreads();
        sh[t] += add;
        __syncthreads();
    }
    if (t < nb) g_bs[t] = sh[t] - v;
}

__global__ void k_s3(int N, int T) {
    int i = blockIdx.x * 256 + threadIdx.x;
    if (i < N) {
        int v = g_rs[i] + g_bs[blockIdx.x];
        g_rs[i] = v;
        g_cur[i] = v;
    }
    if (i == N) g_rs[N] = T;
}

__global__ void k_fill(const int* __restrict__ ei, int E, int N) {
    int t = blockIdx.x * blockDim.x + threadIdx.x;
    if (t >= E + N) return;
    int s, d;
    if (t < E) { s = ei[t]; d = ei[(size_t)E + t]; }
    else       { s = d = t - E; }
    int pos = atomicAdd(&g_cur[d], 1);
    g_esrc[pos] = s;
}

// ---------------- GEMM 1 (register-tiled 4x4) + fused attention logits --------
__global__ void k_gemm1(const float* __restrict__ x, const float* __restrict__ W,
                        const float* __restrict__ a_s, const float* __restrict__ a_d, int N) {
    __shared__ float sW[128 * 64];
    __shared__ float sx[32][68];
    int tid = threadIdx.x;
    for (int i = tid; i < 128 * 16; i += 256)
        *(float4*)&sW[i * 4] = __ldg(&((const float4*)W)[i]);
    int tr = tid >> 4;
    int tc = tid & 15;
    int rowBase = blockIdx.x * 64;
    float acc[4][4] = {};
    int lr = tid >> 2;
    int lk = tid & 3;
    for (int kc = 0; kc < 4; kc++) {
        __syncthreads();
#pragma unroll
        for (int half_ = 0; half_ < 2; half_++) {
            int kl = half_ * 16 + lk * 4;
            int grow = rowBase + lr;
            float4 v = make_float4(0.f, 0.f, 0.f, 0.f);
            if (grow < N) v = __ldg((const float4*)(x + (size_t)grow * 128 + kc * 32 + kl));
            sx[kl + 0][lr] = v.x;
            sx[kl + 1][lr] = v.y;
            sx[kl + 2][lr] = v.z;
            sx[kl + 3][lr] = v.w;
        }
        __syncthreads();
#pragma unroll
        for (int kl = 0; kl < 32; kl++) {
            int k = kc * 32 + kl;
            float4 xv = *(const float4*)&sx[kl][tr * 4];
            float4 wv = *(const float4*)&sW[k * 64 + tc * 4];
            acc[0][0] = fmaf(xv.x, wv.x, acc[0][0]); acc[0][1] = fmaf(xv.x, wv.y, acc[0][1]);
            acc[0][2] = fmaf(xv.x, wv.z, acc[0][2]); acc[0][3] = fmaf(xv.x, wv.w, acc[0][3]);
            acc[1][0] = fmaf(xv.y, wv.x, acc[1][0]); acc[1][1] = fmaf(xv.y, wv.y, acc[1][1]);
            acc[1][2] = fmaf(xv.y, wv.z, acc[1][2]); acc[1][3] = fmaf(xv.y, wv.w, acc[1][3]);
            acc[2][0] = fmaf(xv.z, wv.x, acc[2][0]); acc[2][1] = fmaf(xv.z, wv.y, acc[2][1]);
            acc[2][2] = fmaf(xv.z, wv.z, acc[2][2]); acc[2][3] = fmaf(xv.z, wv.w, acc[2][3]);
            acc[3][0] = fmaf(xv.w, wv.x, acc[3][0]); acc[3][1] = fmaf(xv.w, wv.y, acc[3][1]);
            acc[3][2] = fmaf(xv.w, wv.z, acc[3][2]); acc[3][3] = fmaf(xv.w, wv.w, acc[3][3]);
        }
    }
#pragma unroll
    for (int r = 0; r < 4; r++) {
        int row = rowBase + tr * 4 + r;
        if (row < N) {
            __half2 p[2];
            p[0] = __floats2half2_rn(acc[r][0], acc[r][1]);
            p[1] = __floats2half2_rn(acc[r][2], acc[r][3]);
            *(uint2*)(g_h1h + (size_t)row * 64 + tc * 4) = *(uint2*)p;
        }
    }
    const float4 as4 = __ldg((const float4*)(a_s + tc * 4));
    const float4 ad4 = __ldg((const float4*)(a_d + tc * 4));
    float s[4], d[4];
#pragma unroll
    for (int r = 0; r < 4; r++) {
        s[r] = acc[r][0] * as4.x + acc[r][1] * as4.y + acc[r][2] * as4.z + acc[r][3] * as4.w;
        d[r] = acc[r][0] * ad4.x + acc[r][1] * ad4.y + acc[r][2] * ad4.z + acc[r][3] * ad4.w;
    }
#pragma unroll
    for (int r = 0; r < 4; r++) {
        s[r] += __shfl_xor_sync(0xffffffffu, s[r], 1);
        d[r] += __shfl_xor_sync(0xffffffffu, d[r], 1);
        s[r] += __shfl_xor_sync(0xffffffffu, s[r], 2);
        d[r] += __shfl_xor_sync(0xffffffffu, d[r], 2);
    }
    if ((tc & 3) == 0) {
        int head = tc >> 2;
#pragma unroll
        for (int r = 0; r < 4; r++) {
            int row = rowBase + tr * 4 + r;
            if (row < N) {
                g_als1[(size_t)row * 4 + head] = s[r];
                g_ald1[(size_t)row * 4 + head] = d[r];
            }
        }
    }
}

// ---------------- layer-2 folded attention vectors ----------------
__global__ void k_wvec(const float* __restrict__ W2,
                       const float* __restrict__ a_s2, const float* __restrict__ a_d2) {
    int t = threadIdx.x;
    int h = t >> 6, k = t & 63;
    float s = 0.f, d = 0.f;
    for (int c = 0; c < 32; c++) {
        float wv = W2[k * 128 + h * 32 + c];
        s = fmaf(wv, a_s2[h * 32 + c], s);
        d = fmaf(wv, a_d2[h * 32 + c], d);
    }
    g_ws2[t] = s;
    g_wd2[t] = d;
}

// ---------------- fused layer-1 aggregation + layer-2 logits ----------------
__global__ void k_agg1(const float* __restrict__ b1, int N) {
    __shared__ int   sh_idx[8][32];
    __shared__ float sh_ex[8][32 * 4];
    int wid = threadIdx.x >> 5;
    int w = (blockIdx.x * blockDim.x + threadIdx.x) >> 5;
    int lane = threadIdx.x & 31;
    if (w >= N) return;
    int n = w;
    int start = g_rs[n], end = g_rs[n + 1];
    float4 ad = *(const float4*)(g_ald1 + (size_t)n * 4);

    int head = lane >> 3;
    float acc0 = 0.f, acc1 = 0.f;
    float4 den = make_float4(0.f, 0.f, 0.f, 0.f);
    for (int base = start; base < end; base += 32) {
        int i = base + lane;
        int cnt = min(32, end - base);
        int s = 0;
        float4 ex = make_float4(0.f, 0.f, 0.f, 0.f);
        if (i < end) {
            s = g_esrc[i];
            float4 a = *(const float4*)(g_als1 + (size_t)s * 4);
            ex.x = __expf(lrelu(a.x + ad.x));
            ex.y = __expf(lrelu(a.y + ad.y));
            ex.z = __expf(lrelu(a.z + ad.z));
            ex.w = __expf(lrelu(a.w + ad.w));
            den.x += ex.x; den.y += ex.y; den.z += ex.z; den.w += ex.w;
        }
        sh_idx[wid][lane] = s;
        *(float4*)&sh_ex[wid][lane * 4] = ex;
        __syncwarp();
        if (cnt == 32) {
#pragma unroll 8
            for (int j = 0; j < 32; j++) {
                int   sj  = sh_idx[wid][j];
                float exm = sh_ex[wid][j * 4 + head];
                float2 hv = __half22float2(*(const __half2*)(g_h1h + (size_t)sj * 64 + lane * 2));
                acc0 = fmaf(exm, hv.x, acc0);
                acc1 = fmaf(exm, hv.y, acc1);
            }
        } else {
            for (int j = 0; j < cnt; j++) {
                int   sj  = sh_idx[wid][j];
                float exm = sh_ex[wid][j * 4 + head];
                float2 hv = __half22float2(*(const __half2*)(g_h1h + (size_t)sj * 64 + lane * 2));
                acc0 = fmaf(exm, hv.x, acc0);
                acc1 = fmaf(exm, hv.y, acc1);
            }
        }
        __syncwarp();
    }
#pragma unroll
    for (int o = 16; o; o >>= 1) {
        den.x += __shfl_xor_sync(0xffffffffu, den.x, o);
        den.y += __shfl_xor_sync(0xffffffffu, den.y, o);
        den.z += __shfl_xor_sync(0xffffffffu, den.z, o);
        den.w += __shfl_xor_sync(0xffffffffu, den.w, o);
    }
    float dh = (head == 0) ? den.x : ((head == 1) ? den.y : ((head == 2) ? den.z : den.w));
    float inv = 1.f / (dh + 1e-16f);
    float2 o2;
    o2.x = fmaxf(acc0 * inv + b1[lane * 2], 0.f);
    o2.y = fmaxf(acc1 * inv + b1[lane * 2 + 1], 0.f);
    *(__half2*)(g_x2h + (size_t)n * 64 + lane * 2) = __floats2half2_rn(o2.x, o2.y);

    // fused layer-2 logits from fp32 registers
#pragma unroll
    for (int h = 0; h < 4; h++) {
        float2 ws = *(const float2*)(g_ws2 + h * 64 + lane * 2);
        float2 wd = *(const float2*)(g_wd2 + h * 64 + lane * 2);
        float sv = o2.x * ws.x + o2.y * ws.y;
        float dv = o2.x * wd.x + o2.y * wd.y;
#pragma unroll
        for (int o = 16; o; o >>= 1) {
            sv += __shfl_xor_sync(0xffffffffu, sv, o);
            dv += __shfl_xor_sync(0xffffffffu, dv, o);
        }
        if (lane == 0) {
            g_als2[(size_t)n * 4 + h] = sv;
            g_ald2[(size_t)n * 4 + h] = dv;
        }
    }
}

// ---------------- layer-2 aggregation in x2-space (fp16 gather) ----------
__global__ void k_agg2x(int N) {
    __shared__ int   sh_idx[8][32];
    __shared__ float sh_ex[8][32 * 4];
    int wid = threadIdx.x >> 5;
    int w = (blockIdx.x * blockDim.x + threadIdx.x) >> 5;
    int lane = threadIdx.x & 31;
    if (w >= N) return;
    int n = w;
    int start = g_rs[n], end = g_rs[n + 1];
    float4 ad = *(const float4*)(g_ald2 + (size_t)n * 4);

    float a00 = 0.f, a01 = 0.f, a10 = 0.f, a11 = 0.f;
    float a20 = 0.f, a21 = 0.f, a30 = 0.f, a31 = 0.f;
    float4 den = make_float4(0.f, 0.f, 0.f, 0.f);
    for (int base = start; base < end; base += 32) {
        int i = base + lane;
        int cnt = min(32, end - base);
        int s = 0;
        float4 ex = make_float4(0.f, 0.f, 0.f, 0.f);
        if (i < end) {
            s = g_esrc[i];
            float4 a = *(const float4*)(g_als2 + (size_t)s * 4);
            ex.x = __expf(lrelu(a.x + ad.x));
            ex.y = __expf(lrelu(a.y + ad.y));
            ex.z = __expf(lrelu(a.z + ad.z));
            ex.w = __expf(lrelu(a.w + ad.w));
            den.x += ex.x; den.y += ex.y; den.z += ex.z; den.w += ex.w;
        }
        sh_idx[wid][lane] = s;
        *(float4*)&sh_ex[wid][lane * 4] = ex;
        __syncwarp();
        if (cnt == 32) {
#pragma unroll 4
            for (int j = 0; j < 32; j++) {
                int    sj = sh_idx[wid][j];
                float4 e4 = *(const float4*)&sh_ex[wid][j * 4];
                float2 xv = __half22float2(*(const __half2*)(g_x2h + (size_t)sj * 64 + lane * 2));
                a00 = fmaf(e4.x, xv.x, a00); a01 = fmaf(e4.x, xv.y, a01);
                a10 = fmaf(e4.y, xv.x, a10); a11 = fmaf(e4.y, xv.y, a11);
                a20 = fmaf(e4.z, xv.x, a20); a21 = fmaf(e4.z, xv.y, a21);
                a30 = fmaf(e4.w, xv.x, a30); a31 = fmaf(e4.w, xv.y, a31);
            }
        } else {
            for (int j = 0; j < cnt; j++) {
                int    sj = sh_idx[wid][j];
                float4 e4 = *(const float4*)&sh_ex[wid][j * 4];
                float2 xv = __half22float2(*(const __half2*)(g_x2h + (size_t)sj * 64 + lane * 2));
                a00 = fmaf(e4.x, xv.x, a00); a01 = fmaf(e4.x, xv.y, a01);
                a10 = fmaf(e4.y, xv.x, a10); a11 = fmaf(e4.y, xv.y, a11);
                a20 = fmaf(e4.z, xv.x, a20); a21 = fmaf(e4.z, xv.y, a21);
                a30 = fmaf(e4.w, xv.x, a30); a31 = fmaf(e4.w, xv.y, a31);
            }
        }
        __syncwarp();
    }
#pragma unroll
    for (int o = 16; o; o >>= 1) {
        den.x += __shfl_xor_sync(0xffffffffu, den.x, o);
        den.y += __shfl_xor_sync(0xffffffffu, den.y, o);
        den.z += __shfl_xor_sync(0xffffffffu, den.z, o);
        den.w += __shfl_xor_sync(0xffffffffu, den.w, o);
    }
    float i0 = 1.f / (den.x + 1e-16f);
    float i1 = 1.f / (den.y + 1e-16f);
    float i2 = 1.f / (den.z + 1e-16f);
    float i3 = 1.f / (den.w + 1e-16f);
    float* hg = g_hagg + (size_t)n * 256;
    float2 v;
    v.x = a00 * i0; v.y = a01 * i0; *(float2*)(hg +   0 + lane * 2) = v;
    v.x = a10 * i1; v.y = a11 * i1; *(float2*)(hg +  64 + lane * 2) = v;
    v.x = a20 * i2; v.y = a21 * i2; *(float2*)(hg + 128 + lane * 2) = v;
    v.x = a30 * i3; v.y = a31 * i3; *(float2*)(hg + 192 + lane * 2) = v;
}

// ---------------- post-agg GEMM2 + bias + relu + pooled sums ----------------
__global__ void k_out(const float* __restrict__ W2, const float* __restrict__ b2,
                      const int* __restrict__ batch, int N) {
    __shared__ float sW[64 * 128];
    for (int i = threadIdx.x; i < 64 * 32; i += 256)
        *(float4*)&sW[i * 4] = __ldg(&((const float4*)W2)[i]);
    __syncthreads();
    int c4   = threadIdx.x & 31;
    int rowl = threadIdx.x >> 5;
    int head = c4 >> 3;
    const float4 bb = __ldg((const float4*)(b2 + c4 * 4));
    int rowBase = blockIdx.x * 64;
#pragma unroll 1
    for (int rb = 0; rb < 8; rb++) {
        int row = rowBase + rb * 8 + rowl;
        if (row >= N) break;
        const float4* hr = (const float4*)(g_hagg + (size_t)row * 256 + head * 64);
        float acc0 = 0.f, acc1 = 0.f, acc2 = 0.f, acc3 = 0.f;
#pragma unroll
        for (int k4 = 0; k4 < 16; k4++) {
            float4 xv = hr[k4];
            float4 w0 = *(const float4*)&sW[(k4 * 4 + 0) * 128 + c4 * 4];
            float4 w1 = *(const float4*)&sW[(k4 * 4 + 1) * 128 + c4 * 4];
            float4 w2 = *(const float4*)&sW[(k4 * 4 + 2) * 128 + c4 * 4];
            float4 w3 = *(const float4*)&sW[(k4 * 4 + 3) * 128 + c4 * 4];
            acc0 = fmaf(xv.x, w0.x, acc0); acc1 = fmaf(xv.x, w0.y, acc1);
            acc2 = fmaf(xv.x, w0.z, acc2); acc3 = fmaf(xv.x, w0.w, acc3);
            acc0 = fmaf(xv.y, w1.x, acc0); acc1 = fmaf(xv.y, w1.y, acc1);
            acc2 = fmaf(xv.y, w1.z, acc2); acc3 = fmaf(xv.y, w1.w, acc3);
            acc0 = fmaf(xv.z, w2.x, acc0); acc1 = fmaf(xv.z, w2.y, acc1);
            acc2 = fmaf(xv.z, w2.z, acc2); acc3 = fmaf(xv.z, w2.w, acc3);
            acc0 = fmaf(xv.w, w3.x, acc0); acc1 = fmaf(xv.w, w3.y, acc1);
            acc2 = fmaf(xv.w, w3.z, acc2); acc3 = fmaf(xv.w, w3.w, acc3);
        }
        float o0 = fmaxf(acc0 + bb.x, 0.f);
        float o1 = fmaxf(acc1 + bb.y, 0.f);
        float o2 = fmaxf(acc2 + bb.z, 0.f);
        float o3 = fmaxf(acc3 + bb.w, 0.f);
        int g = batch[row];
        red4(g_sums + (size_t)g * 128 + c4 * 4, o0, o1, o2, o3);
        if (c4 == 0) atomicAdd(&g_cnt[g], 1.f);
    }
}

// ---------------- pool divide ----------------
__global__ void k_pool(float* __restrict__ out, int G) {
    int t = blockIdx.x * blockDim.x + threadIdx.x;
    if (t >= G * 32) return;
    int g = t >> 5;
    float inv = 1.f / fmaxf(g_cnt[g], 1.f);
    float4 s = *(const float4*)(g_sums + (size_t)t * 4);
    float4 o = { s.x * inv, s.y * inv, s.z * inv, s.w * inv };
    *(float4*)(out + (size_t)t * 4) = o;
}

// ---------------- launch ----------------
extern "C" void kernel_launch(void* const* d_in, const int* in_sizes, int n_in,
                              void* d_out, int out_size) {
    const float* x     = (const float*)d_in[0];
    const int*   ei    = (const int*)d_in[1];
    const int*   batch = (const int*)d_in[3];
    const float* W1    = (const float*)d_in[4];
    const float* a_s1  = (const float*)d_in[5];
    const float* a_d1  = (const float*)d_in[6];
    const float* b1    = (const float*)d_in[7];
    const float* W2    = (const float*)d_in[8];
    const float* a_s2  = (const float*)d_in[9];
    const float* a_d2  = (const float*)d_in[10];
    const float* b2    = (const float*)d_in[11];
    float*       out   = (float*)d_out;

    int N = in_sizes[0] / 128;
    int E = in_sizes[1] / 2;
    int G = out_size / 128;
    int T = E + N;

    void *pdeg, *ps, *pc;
    cudaGetSymbolAddress(&pdeg, g_deg);
    cudaGetSymbolAddress(&ps, g_sums);
    cudaGetSymbolAddress(&pc, g_cnt);
    cudaMemsetAsync(pdeg, 0, (size_t)N * 4);
    cudaMemsetAsync(ps, 0, (size_t)G * 128 * 4);
    cudaMemsetAsync(pc, 0, (size_t)G * 4);

    int nb = (N + 255) / 256;

    // --- CSR build ---
    k_deg<<<(E + 255) / 256, 256>>>(ei, E);
    k_s1<<<nb, 256>>>(N);
    k_s2<<<1, 512>>>(nb);
    k_s3<<<(N + 256) / 256, 256>>>(N, T);
    k_fill<<<(T + 255) / 256, 256>>>(ei, E, N);

    // --- fold W2 @ a2 ---
    k_wvec<<<1, 256>>>(W2, a_s2, a_d2);

    // --- layer 1 (+ fused layer-2 logits) ---
    k_gemm1<<<(N + 63) / 64, 256>>>(x, W1, a_s1, a_d1, N);
    k_agg1<<<(N + 7) / 8, 256>>>(b1, N);

    // --- layer 2 ---
    k_agg2x<<<(N + 7) / 8, 256>>>(N);
    k_out<<<(N + 63) / 64, 256>>>(W2, b2, batch, N);

    // --- pool ---
    k_pool<<<(G * 32 + 255) / 256, 256>>>(out, G);
}

// round 14
// speedup vs baseline: 3.4658x; 1.0792x over previous
#include <cuda_runtime.h>
#include <cuda_fp16.h>

// ---------------- problem constants ----------------
#define NMAX 100000
#define GMAX 2048
#define EMAXT 3301024   // E + N + margin

// ---------------- scratch ----------------
__device__ __align__(16) __half g_h1h[NMAX * 64];     // h1 in fp16
__device__ __align__(16) float  g_als1[NMAX * 4];
__device__ __align__(16) float  g_ald1[NMAX * 4];
__device__ __align__(16) __half g_x2h[NMAX * 64];     // x2 in fp16
__device__ __align__(16) float  g_als2[NMAX * 4];
__device__ __align__(16) float  g_ald2[NMAX * 4];
__device__ __align__(16) __half g_haggh[NMAX * 256];  // [n][head][64] fp16
__device__ __align__(16) float  g_ws2[256];
__device__ __align__(16) float  g_wd2[256];
__device__ __align__(16) float  g_sums[GMAX * 128];
__device__ __align__(16) float  g_cnt[GMAX];
// CSR
__device__ int g_deg[NMAX];
__device__ int g_rs[NMAX + 1];
__device__ int g_cur[NMAX];
__device__ int g_esrc[EMAXT];
__device__ int g_bs[512];

// ---------------- helpers ----------------
__device__ __forceinline__ float lrelu(float e) { return e > 0.f ? e : 0.2f * e; }
__device__ __forceinline__ void red4(float* p, float a, float b, float c, float d) {
    asm volatile("red.global.add.v4.f32 [%0], {%1,%2,%3,%4};"
                 :: "l"(p), "f"(a), "f"(b), "f"(c), "f"(d) : "memory");
}

// ---------------- CSR build ----------------
__global__ void k_deg(const int* __restrict__ ei, int E) {
    int t = blockIdx.x * blockDim.x + threadIdx.x;
    if (t >= E) return;
    atomicAdd(&g_deg[ei[(size_t)E + t]], 1);
}

__global__ void k_s1(int N) {
    __shared__ int sh[256];
    int t = threadIdx.x;
    int i = blockIdx.x * 256 + t;
    int v = (i < N) ? g_deg[i] + 1 : 0;   // +1 self loop
    sh[t] = v;
    __syncthreads();
    for (int o = 1; o < 256; o <<= 1) {
        int add = (t >= o) ? sh[t - o] : 0;
        __syncthreads();
        sh[t] += add;
        __syncthreads();
    }
    if (i < N) g_rs[i] = sh[t] - v;
    if (t == 255) g_bs[blockIdx.x] = sh[255];
}

__global__ void k_s2(int nb) {
    __shared__ int sh[512];
    int t = threadIdx.x;
    int v = (t < nb) ? g_bs[t] : 0;
    sh[t] = v;
    __syncthreads();
    for (int o = 1; o < 512; o <<= 1) {
        int add = (t >= o) ? sh[t - o] : 0;
        __syncthreads();
        sh[t] += add;
        __syncthreads();
    }
    if (t < nb) g_bs[t] = sh[t] - v;
}

__global__ void k_s3(int N, int T) {
    int i = blockIdx.x * 256 + threadIdx.x;
    if (i < N) {
        int v = g_rs[i] + g_bs[blockIdx.x];
        g_rs[i] = v;
        g_cur[i] = v;
    }
    if (i == N) g_rs[N] = T;
}

__global__ void k_fill(const int* __restrict__ ei, int E, int N) {
    int t = blockIdx.x * blockDim.x + threadIdx.x;
    if (t >= E + N) return;
    int s, d;
    if (t < E) { s = ei[t]; d = ei[(size_t)E + t]; }
    else       { s = d = t - E; }
    int pos = atomicAdd(&g_cur[d], 1);
    g_esrc[pos] = s;
}

// ---------------- GEMM 1 (register-tiled 4x4) + fused attention logits --------
__global__ void k_gemm1(const float* __restrict__ x, const float* __restrict__ W,
                        const float* __restrict__ a_s, const float* __restrict__ a_d, int N) {
    __shared__ float sW[128 * 64];
    __shared__ float sx[32][68];
    int tid = threadIdx.x;
    for (int i = tid; i < 128 * 16; i += 256)
        *(float4*)&sW[i * 4] = __ldg(&((const float4*)W)[i]);
    int tr = tid >> 4;
    int tc = tid & 15;
    int rowBase = blockIdx.x * 64;
    float acc[4][4] = {};
    int lr = tid >> 2;
    int lk = tid & 3;
    for (int kc = 0; kc < 4; kc++) {
        __syncthreads();
#pragma unroll
        for (int half_ = 0; half_ < 2; half_++) {
            int kl = half_ * 16 + lk * 4;
            int grow = rowBase + lr;
            float4 v = make_float4(0.f, 0.f, 0.f, 0.f);
            if (grow < N) v = __ldg((const float4*)(x + (size_t)grow * 128 + kc * 32 + kl));
            sx[kl + 0][lr] = v.x;
            sx[kl + 1][lr] = v.y;
            sx[kl + 2][lr] = v.z;
            sx[kl + 3][lr] = v.w;
        }
        __syncthreads();
#pragma unroll
        for (int kl = 0; kl < 32; kl++) {
            int k = kc * 32 + kl;
            float4 xv = *(const float4*)&sx[kl][tr * 4];
            float4 wv = *(const float4*)&sW[k * 64 + tc * 4];
            acc[0][0] = fmaf(xv.x, wv.x, acc[0][0]); acc[0][1] = fmaf(xv.x, wv.y, acc[0][1]);
            acc[0][2] = fmaf(xv.x, wv.z, acc[0][2]); acc[0][3] = fmaf(xv.x, wv.w, acc[0][3]);
            acc[1][0] = fmaf(xv.y, wv.x, acc[1][0]); acc[1][1] = fmaf(xv.y, wv.y, acc[1][1]);
            acc[1][2] = fmaf(xv.y, wv.z, acc[1][2]); acc[1][3] = fmaf(xv.y, wv.w, acc[1][3]);
            acc[2][0] = fmaf(xv.z, wv.x, acc[2][0]); acc[2][1] = fmaf(xv.z, wv.y, acc[2][1]);
            acc[2][2] = fmaf(xv.z, wv.z, acc[2][2]); acc[2][3] = fmaf(xv.z, wv.w, acc[2][3]);
            acc[3][0] = fmaf(xv.w, wv.x, acc[3][0]); acc[3][1] = fmaf(xv.w, wv.y, acc[3][1]);
            acc[3][2] = fmaf(xv.w, wv.z, acc[3][2]); acc[3][3] = fmaf(xv.w, wv.w, acc[3][3]);
        }
    }
#pragma unroll
    for (int r = 0; r < 4; r++) {
        int row = rowBase + tr * 4 + r;
        if (row < N) {
            __half2 p[2];
            p[0] = __floats2half2_rn(acc[r][0], acc[r][1]);
            p[1] = __floats2half2_rn(acc[r][2], acc[r][3]);
            *(uint2*)(g_h1h + (size_t)row * 64 + tc * 4) = *(uint2*)p;
        }
    }
    const float4 as4 = __ldg((const float4*)(a_s + tc * 4));
    const float4 ad4 = __ldg((const float4*)(a_d + tc * 4));
    float s[4], d[4];
#pragma unroll
    for (int r = 0; r < 4; r++) {
        s[r] = acc[r][0] * as4.x + acc[r][1] * as4.y + acc[r][2] * as4.z + acc[r][3] * as4.w;
        d[r] = acc[r][0] * ad4.x + acc[r][1] * ad4.y + acc[r][2] * ad4.z + acc[r][3] * ad4.w;
    }
#pragma unroll
    for (int r = 0; r < 4; r++) {
        s[r] += __shfl_xor_sync(0xffffffffu, s[r], 1);
        d[r] += __shfl_xor_sync(0xffffffffu, d[r], 1);
        s[r] += __shfl_xor_sync(0xffffffffu, s[r], 2);
        d[r] += __shfl_xor_sync(0xffffffffu, d[r], 2);
    }
    if ((tc & 3) == 0) {
        int head = tc >> 2;
#pragma unroll
        for (int r = 0; r < 4; r++) {
            int row = rowBase + tr * 4 + r;
            if (row < N) {
                g_als1[(size_t)row * 4 + head] = s[r];
                g_ald1[(size_t)row * 4 + head] = d[r];
            }
        }
    }
}

// ---------------- layer-2 folded attention vectors ----------------
__global__ void k_wvec(const float* __restrict__ W2,
                       const float* __restrict__ a_s2, const float* __restrict__ a_d2) {
    int t = threadIdx.x;
    int h = t >> 6, k = t & 63;
    float s = 0.f, d = 0.f;
    for (int c = 0; c < 32; c++) {
        float wv = W2[k * 128 + h * 32 + c];
        s = fmaf(wv, a_s2[h * 32 + c], s);
        d = fmaf(wv, a_d2[h * 32 + c], d);
    }
    g_ws2[t] = s;
    g_wd2[t] = d;
}

// ---------------- fused layer-1 aggregation + layer-2 logits ----------------
__global__ void k_agg1(const float* __restrict__ b1, int N) {
    __shared__ int   sh_idx[8][32];
    __shared__ float sh_ex[8][32 * 4];
    int wid = threadIdx.x >> 5;
    int w = (blockIdx.x * blockDim.x + threadIdx.x) >> 5;
    int lane = threadIdx.x & 31;
    if (w >= N) return;
    int n = w;
    int start = g_rs[n], end = g_rs[n + 1];
    float4 ad = *(const float4*)(g_ald1 + (size_t)n * 4);

    int head = lane >> 3;
    float acc0 = 0.f, acc1 = 0.f;
    float4 den = make_float4(0.f, 0.f, 0.f, 0.f);
    for (int base = start; base < end; base += 32) {
        int i = base + lane;
        int cnt = min(32, end - base);
        int s = 0;
        float4 ex = make_float4(0.f, 0.f, 0.f, 0.f);
        if (i < end) {
            s = g_esrc[i];
            float4 a = *(const float4*)(g_als1 + (size_t)s * 4);
            ex.x = __expf(lrelu(a.x + ad.x));
            ex.y = __expf(lrelu(a.y + ad.y));
            ex.z = __expf(lrelu(a.z + ad.z));
            ex.w = __expf(lrelu(a.w + ad.w));
            den.x += ex.x; den.y += ex.y; den.z += ex.z; den.w += ex.w;
        }
        sh_idx[wid][lane] = s;
        *(float4*)&sh_ex[wid][lane * 4] = ex;
        __syncwarp();
        if (cnt == 32) {
#pragma unroll 8
            for (int j = 0; j < 32; j++) {
                int   sj  = sh_idx[wid][j];
                float exm = sh_ex[wid][j * 4 + head];
                float2 hv = __half22float2(*(const __half2*)(g_h1h + (size_t)sj * 64 + lane * 2));
                acc0 = fmaf(exm, hv.x, acc0);
                acc1 = fmaf(exm, hv.y, acc1);
            }
        } else {
            for (int j = 0; j < cnt; j++) {
                int   sj  = sh_idx[wid][j];
                float exm = sh_ex[wid][j * 4 + head];
                float2 hv = __half22float2(*(const __half2*)(g_h1h + (size_t)sj * 64 + lane * 2));
                acc0 = fmaf(exm, hv.x, acc0);
                acc1 = fmaf(exm, hv.y, acc1);
            }
        }
        __syncwarp();
    }
#pragma unroll
    for (int o = 16; o; o >>= 1) {
        den.x += __shfl_xor_sync(0xffffffffu, den.x, o);
        den.y += __shfl_xor_sync(0xffffffffu, den.y, o);
        den.z += __shfl_xor_sync(0xffffffffu, den.z, o);
        den.w += __shfl_xor_sync(0xffffffffu, den.w, o);
    }
    float dh = (head == 0) ? den.x : ((head == 1) ? den.y : ((head == 2) ? den.z : den.w));
    float inv = 1.f / (dh + 1e-16f);
    float2 o2;
    o2.x = fmaxf(acc0 * inv + b1[lane * 2], 0.f);
    o2.y = fmaxf(acc1 * inv + b1[lane * 2 + 1], 0.f);
    *(__half2*)(g_x2h + (size_t)n * 64 + lane * 2) = __floats2half2_rn(o2.x, o2.y);

    // fused layer-2 logits from fp32 registers
#pragma unroll
    for (int h = 0; h < 4; h++) {
        float2 ws = *(const float2*)(g_ws2 + h * 64 + lane * 2);
        float2 wd = *(const float2*)(g_wd2 + h * 64 + lane * 2);
        float sv = o2.x * ws.x + o2.y * ws.y;
        float dv = o2.x * wd.x + o2.y * wd.y;
#pragma unroll
        for (int o = 16; o; o >>= 1) {
            sv += __shfl_xor_sync(0xffffffffu, sv, o);
            dv += __shfl_xor_sync(0xffffffffu, dv, o);
        }
        if (lane == 0) {
            g_als2[(size_t)n * 4 + h] = sv;
            g_ald2[(size_t)n * 4 + h] = dv;
        }
    }
}

// ---------------- layer-2 aggregation in x2-space (fp16 gather) ----------
__global__ void k_agg2x(int N) {
    __shared__ int   sh_idx[8][32];
    __shared__ float sh_ex[8][32 * 4];
    int wid = threadIdx.x >> 5;
    int w = (blockIdx.x * blockDim.x + threadIdx.x) >> 5;
    int lane = threadIdx.x & 31;
    if (w >= N) return;
    int n = w;
    int start = g_rs[n], end = g_rs[n + 1];
    float4 ad = *(const float4*)(g_ald2 + (size_t)n * 4);

    float a00 = 0.f, a01 = 0.f, a10 = 0.f, a11 = 0.f;
    float a20 = 0.f, a21 = 0.f, a30 = 0.f, a31 = 0.f;
    float4 den = make_float4(0.f, 0.f, 0.f, 0.f);
    for (int base = start; base < end; base += 32) {
        int i = base + lane;
        int cnt = min(32, end - base);
        int s = 0;
        float4 ex = make_float4(0.f, 0.f, 0.f, 0.f);
        if (i < end) {
            s = g_esrc[i];
            float4 a = *(const float4*)(g_als2 + (size_t)s * 4);
            ex.x = __expf(lrelu(a.x + ad.x));
            ex.y = __expf(lrelu(a.y + ad.y));
            ex.z = __expf(lrelu(a.z + ad.z));
            ex.w = __expf(lrelu(a.w + ad.w));
            den.x += ex.x; den.y += ex.y; den.z += ex.z; den.w += ex.w;
        }
        sh_idx[wid][lane] = s;
        *(float4*)&sh_ex[wid][lane * 4] = ex;
        __syncwarp();
        if (cnt == 32) {
#pragma unroll 4
            for (int j = 0; j < 32; j++) {
                int    sj = sh_idx[wid][j];
                float4 e4 = *(const float4*)&sh_ex[wid][j * 4];
                float2 xv = __half22float2(*(const __half2*)(g_x2h + (size_t)sj * 64 + lane * 2));
                a00 = fmaf(e4.x, xv.x, a00); a01 = fmaf(e4.x, xv.y, a01);
                a10 = fmaf(e4.y, xv.x, a10); a11 = fmaf(e4.y, xv.y, a11);
                a20 = fmaf(e4.z, xv.x, a20); a21 = fmaf(e4.z, xv.y, a21);
                a30 = fmaf(e4.w, xv.x, a30); a31 = fmaf(e4.w, xv.y, a31);
            }
        } else {
            for (int j = 0; j < cnt; j++) {
                int    sj = sh_idx[wid][j];
                float4 e4 = *(const float4*)&sh_ex[wid][j * 4];
                float2 xv = __half22float2(*(const __half2*)(g_x2h + (size_t)sj * 64 + lane * 2));
                a00 = fmaf(e4.x, xv.x, a00); a01 = fmaf(e4.x, xv.y, a01);
                a10 = fmaf(e4.y, xv.x, a10); a11 = fmaf(e4.y, xv.y, a11);
                a20 = fmaf(e4.z, xv.x, a20); a21 = fmaf(e4.z, xv.y, a21);
                a30 = fmaf(e4.w, xv.x, a30); a31 = fmaf(e4.w, xv.y, a31);
            }
        }
        __syncwarp();
    }
#pragma unroll
    for (int o = 16; o; o >>= 1) {
        den.x += __shfl_xor_sync(0xffffffffu, den.x, o);
        den.y += __shfl_xor_sync(0xffffffffu, den.y, o);
        den.z += __shfl_xor_sync(0xffffffffu, den.z, o);
        den.w += __shfl_xor_sync(0xffffffffu, den.w, o);
    }
    float i0 = 1.f / (den.x + 1e-16f);
    float i1 = 1.f / (den.y + 1e-16f);
    float i2 = 1.f / (den.z + 1e-16f);
    float i3 = 1.f / (den.w + 1e-16f);
    __half* hg = g_haggh + (size_t)n * 256;
    *(__half2*)(hg +   0 + lane * 2) = __floats2half2_rn(a00 * i0, a01 * i0);
    *(__half2*)(hg +  64 + lane * 2) = __floats2half2_rn(a10 * i1, a11 * i1);
    *(__half2*)(hg + 128 + lane * 2) = __floats2half2_rn(a20 * i2, a21 * i2);
    *(__half2*)(hg + 192 + lane * 2) = __floats2half2_rn(a30 * i3, a31 * i3);
}

// ---------------- post-agg GEMM2 + bias + relu + pooled sums ----------------
__global__ void k_out(const float* __restrict__ W2, const float* __restrict__ b2,
                      const int* __restrict__ batch, int N) {
    __shared__ float sW[64 * 128];
    for (int i = threadIdx.x; i < 64 * 32; i += 256)
        *(float4*)&sW[i * 4] = __ldg(&((const float4*)W2)[i]);
    __syncthreads();
    int c4   = threadIdx.x & 31;
    int rowl = threadIdx.x >> 5;
    int head = c4 >> 3;
    const float4 bb = __ldg((const float4*)(b2 + c4 * 4));
    int rowBase = blockIdx.x * 64;
#pragma unroll 1
    for (int rb = 0; rb < 8; rb++) {
        int row = rowBase + rb * 8 + rowl;
        if (row >= N) break;
        const uint2* hr = (const uint2*)(g_haggh + (size_t)row * 256 + head * 64);
        float acc0 = 0.f, acc1 = 0.f, acc2 = 0.f, acc3 = 0.f;
#pragma unroll
        for (int k4 = 0; k4 < 16; k4++) {
            uint2 u = hr[k4];
            float2 f0 = __half22float2(*(const __half2*)&u.x);
            float2 f1 = __half22float2(*(const __half2*)&u.y);
            float4 w0 = *(const float4*)&sW[(k4 * 4 + 0) * 128 + c4 * 4];
            float4 w1 = *(const float4*)&sW[(k4 * 4 + 1) * 128 + c4 * 4];
            float4 w2 = *(const float4*)&sW[(k4 * 4 + 2) * 128 + c4 * 4];
            float4 w3 = *(const float4*)&sW[(k4 * 4 + 3) * 128 + c4 * 4];
            acc0 = fmaf(f0.x, w0.x, acc0); acc1 = fmaf(f0.x, w0.y, acc1);
            acc2 = fmaf(f0.x, w0.z, acc2); acc3 = fmaf(f0.x, w0.w, acc3);
            acc0 = fmaf(f0.y, w1.x, acc0); acc1 = fmaf(f0.y, w1.y, acc1);
            acc2 = fmaf(f0.y, w1.z, acc2); acc3 = fmaf(f0.y, w1.w, acc3);
            acc0 = fmaf(f1.x, w2.x, acc0); acc1 = fmaf(f1.x, w2.y, acc1);
            acc2 = fmaf(f1.x, w2.z, acc2); acc3 = fmaf(f1.x, w2.w, acc3);
            acc0 = fmaf(f1.y, w3.x, acc0); acc1 = fmaf(f1.y, w3.y, acc1);
            acc2 = fmaf(f1.y, w3.z, acc2); acc3 = fmaf(f1.y, w3.w, acc3);
        }
        float o0 = fmaxf(acc0 + bb.x, 0.f);
        float o1 = fmaxf(acc1 + bb.y, 0.f);
        float o2 = fmaxf(acc2 + bb.z, 0.f);
        float o3 = fmaxf(acc3 + bb.w, 0.f);
        int g = batch[row];
        red4(g_sums + (size_t)g * 128 + c4 * 4, o0, o1, o2, o3);
        if (c4 == 0) atomicAdd(&g_cnt[g], 1.f);
    }
}

// ---------------- pool divide ----------------
__global__ void k_pool(float* __restrict__ out, int G) {
    int t = blockIdx.x * blockDim.x + threadIdx.x;
    if (t >= G * 32) return;
    int g = t >> 5;
    float inv = 1.f / fmaxf(g_cnt[g], 1.f);
    float4 s = *(const float4*)(g_sums + (size_t)t * 4);
    float4 o = { s.x * inv, s.y * inv, s.z * inv, s.w * inv };
    *(float4*)(out + (size_t)t * 4) = o;
}

// ---------------- launch ----------------
extern "C" void kernel_launch(void* const* d_in, const int* in_sizes, int n_in,
                              void* d_out, int out_size) {
    const float* x     = (const float*)d_in[0];
    const int*   ei    = (const int*)d_in[1];
    const int*   batch = (const int*)d_in[3];
    const float* W1    = (const float*)d_in[4];
    const float* a_s1  = (const float*)d_in[5];
    const float* a_d1  = (const float*)d_in[6];
    const float* b1    = (const float*)d_in[7];
    const float* W2    = (const float*)d_in[8];
    const float* a_s2  = (const float*)d_in[9];
    const float* a_d2  = (const float*)d_in[10];
    const float* b2    = (const float*)d_in[11];
    float*       out   = (float*)d_out;

    int N = in_sizes[0] / 128;
    int E = in_sizes[1] / 2;
    int G = out_size / 128;
    int T = E + N;

    void *pdeg, *ps, *pc;
    cudaGetSymbolAddress(&pdeg, g_deg);
    cudaGetSymbolAddress(&ps, g_sums);
    cudaGetSymbolAddress(&pc, g_cnt);

    // fork a non-blocking side stream for the CSR-independent GEMM work
    cudaStream_t s2;
    cudaStreamCreateWithFlags(&s2, cudaStreamNonBlocking);
    cudaEvent_t eFork, eJoin;
    cudaEventCreateWithFlags(&eFork, cudaEventDisableTiming);
    cudaEventCreateWithFlags(&eJoin, cudaEventDisableTiming);

    cudaEventRecord(eFork, 0);
    cudaStreamWaitEvent(s2, eFork, 0);

    // side stream: fold W2@a2, then GEMM1 (+logits)
    k_wvec<<<1, 256, 0, s2>>>(W2, a_s2, a_d2);
    k_gemm1<<<(N + 63) / 64, 256, 0, s2>>>(x, W1, a_s1, a_d1, N);
    cudaEventRecord(eJoin, s2);

    // main stream: memsets + CSR build
    cudaMemsetAsync(pdeg, 0, (size_t)N * 4);
    cudaMemsetAsync(ps, 0, (size_t)G * 128 * 4);
    cudaMemsetAsync(pc, 0, (size_t)G * 4);

    int nb = (N + 255) / 256;
    k_deg<<<(E + 255) / 256, 256>>>(ei, E);
    k_s1<<<nb, 256>>>(N);
    k_s2<<<1, 512>>>(nb);
    k_s3<<<(N + 256) / 256, 256>>>(N, T);
    k_fill<<<(T + 255) / 256, 256>>>(ei, E, N);

    // join: aggregation needs both CSR and GEMM1 results
    cudaStreamWaitEvent(0, eJoin, 0);

    k_agg1<<<(N + 7) / 8, 256>>>(b1, N);
    k_agg2x<<<(N + 7) / 8, 256>>>(N);
    k_out<<<(N + 63) / 64, 256>>>(W2, b2, batch, N);
    k_pool<<<(G * 32 + 255) / 256, 256>>>(out, G);

    // NOTE: stream/event objects are intentionally not destroyed here —
    // destroying capture-referenced objects mid-capture is invalid, and
    // kernel_launch runs only a handful of times (host-side leak only).
}

// round 16
// speedup vs baseline: 3.9651x; 1.1441x over previous
#include <cuda_runtime.h>
#include <cuda_fp16.h>

// ---------------- problem constants ----------------
#define NMAX 100000
#define GMAX 2048
#define EMAXT 3301024   // E + N + margin

// ---------------- scratch ----------------
__device__ __align__(16) __half g_h1h[NMAX * 64];     // h1 in fp16
__device__ __align__(16) float  g_als1[NMAX * 4];
__device__ __align__(16) float  g_ald1[NMAX * 4];
__device__ __align__(16) __half g_x2h[NMAX * 64];     // x2 in fp16
__device__ __align__(16) float  g_als2[NMAX * 4];
__device__ __align__(16) float  g_ald2[NMAX * 4];
__device__ __align__(16) __half g_haggh[NMAX * 256];  // [n][head][64] fp16
__device__ __align__(16) float  g_ws2[256];
__device__ __align__(16) float  g_wd2[256];
__device__ __align__(16) float  g_sums[GMAX * 128];
__device__ __align__(16) float  g_cnt[GMAX];
// CSR
__device__ int g_deg[NMAX];
__device__ int g_rs[NMAX + 1];
__device__ int g_cur[NMAX];
__device__ int g_esrc[EMAXT];
__device__ int g_bs[512];

// ---------------- helpers ----------------
__device__ __forceinline__ float lrelu(float e) { return e > 0.f ? e : 0.2f * e; }
__device__ __forceinline__ void red4(float* p, float a, float b, float c, float d) {
    asm volatile("red.global.add.v4.f32 [%0], {%1,%2,%3,%4};"
                 :: "l"(p), "f"(a), "f"(b), "f"(c), "f"(d) : "memory");
}

// ---------------- CSR build ----------------
__global__ void k_deg(const int* __restrict__ ei, int E) {
    int t = blockIdx.x * blockDim.x + threadIdx.x;
    if (t >= E) return;
    atomicAdd(&g_deg[ei[(size_t)E + t]], 1);
}

__global__ void k_s1(int N) {
    __shared__ int sh[256];
    int t = threadIdx.x;
    int i = blockIdx.x * 256 + t;
    int v = (i < N) ? g_deg[i] + 1 : 0;   // +1 self loop
    sh[t] = v;
    __syncthreads();
    for (int o = 1; o < 256; o <<= 1) {
        int add = (t >= o) ? sh[t - o] : 0;
        __syncthreads();
        sh[t] += add;
        __syncthreads();
    }
    if (i < N) g_rs[i] = sh[t] - v;
    if (t == 255) g_bs[blockIdx.x] = sh[255];
}

__global__ void k_s2(int nb) {
    __shared__ int sh[512];
    int t = threadIdx.x;
    int v = (t < nb) ? g_bs[t] : 0;
    sh[t] = v;
    __syncthreads();
    for (int o = 1; o < 512; o <<= 1) {
        int add = (t >= o) ? sh[t - o] : 0;
        __syncthreads();
        sh[t] += add;
        __syncthreads();
    }
    if (t < nb) g_bs[t] = sh[t] - v;
}

__global__ void k_s3(int N, int T) {
    int i = blockIdx.x * 256 + threadIdx.x;
    if (i < N) {
        int v = g_rs[i] + g_bs[blockIdx.x];
        g_rs[i] = v;
        g_cur[i] = v;
    }
    if (i == N) g_rs[N] = T;
}

__global__ void k_fill(const int* __restrict__ ei, int E, int N) {
    int t = blockIdx.x * blockDim.x + threadIdx.x;
    if (t >= E + N) return;
    int s, d;
    if (t < E) { s = ei[t]; d = ei[(size_t)E + t]; }
    else       { s = d = t - E; }
    int pos = atomicAdd(&g_cur[d], 1);
    g_esrc[pos] = s;
}

// ---------------- GEMM 1 (register-tiled 4x4) + fused attention logits --------
__global__ void k_gemm1(const float* __restrict__ x, const float* __restrict__ W,
                        const float* __restrict__ a_s, const float* __restrict__ a_d, int N) {
    __shared__ float sW[128 * 64];
    __shared__ float sx[32][68];
    int tid = threadIdx.x;
    for (int i = tid; i < 128 * 16; i += 256)
        *(float4*)&sW[i * 4] = __ldg(&((const float4*)W)[i]);
    int tr = tid >> 4;
    int tc = tid & 15;
    int rowBase = blockIdx.x * 64;
    float acc[4][4] = {};
    int lr = tid >> 2;
    int lk = tid & 3;
    for (int kc = 0; kc < 4; kc++) {
        __syncthreads();
#pragma unroll
        for (int half_ = 0; half_ < 2; half_++) {
            int kl = half_ * 16 + lk * 4;
            int grow = rowBase + lr;
            float4 v = make_float4(0.f, 0.f, 0.f, 0.f);
            if (grow < N) v = __ldg((const float4*)(x + (size_t)grow * 128 + kc * 32 + kl));
            sx[kl + 0][lr] = v.x;
            sx[kl + 1][lr] = v.y;
            sx[kl + 2][lr] = v.z;
            sx[kl + 3][lr] = v.w;
        }
        __syncthreads();
#pragma unroll
        for (int kl = 0; kl < 32; kl++) {
            int k = kc * 32 + kl;
            float4 xv = *(const float4*)&sx[kl][tr * 4];
            float4 wv = *(const float4*)&sW[k * 64 + tc * 4];
            acc[0][0] = fmaf(xv.x, wv.x, acc[0][0]); acc[0][1] = fmaf(xv.x, wv.y, acc[0][1]);
            acc[0][2] = fmaf(xv.x, wv.z, acc[0][2]); acc[0][3] = fmaf(xv.x, wv.w, acc[0][3]);
            acc[1][0] = fmaf(xv.y, wv.x, acc[1][0]); acc[1][1] = fmaf(xv.y, wv.y, acc[1][1]);
            acc[1][2] = fmaf(xv.y, wv.z, acc[1][2]); acc[1][3] = fmaf(xv.y, wv.w, acc[1][3]);
            acc[2][0] = fmaf(xv.z, wv.x, acc[2][0]); acc[2][1] = fmaf(xv.z, wv.y, acc[2][1]);
            acc[2][2] = fmaf(xv.z, wv.z, acc[2][2]); acc[2][3] = fmaf(xv.z, wv.w, acc[2][3]);
            acc[3][0] = fmaf(xv.w, wv.x, acc[3][0]); acc[3][1] = fmaf(xv.w, wv.y, acc[3][1]);
            acc[3][2] = fmaf(xv.w, wv.z, acc[3][2]); acc[3][3] = fmaf(xv.w, wv.w, acc[3][3]);
        }
    }
#pragma unroll
    for (int r = 0; r < 4; r++) {
        int row = rowBase + tr * 4 + r;
        if (row < N) {
            __half2 p[2];
            p[0] = __floats2half2_rn(acc[r][0], acc[r][1]);
            p[1] = __floats2half2_rn(acc[r][2], acc[r][3]);
            *(uint2*)(g_h1h + (size_t)row * 64 + tc * 4) = *(uint2*)p;
        }
    }
    const float4 as4 = __ldg((const float4*)(a_s + tc * 4));
    const float4 ad4 = __ldg((const float4*)(a_d + tc * 4));
    float s[4], d[4];
#pragma unroll
    for (int r = 0; r < 4; r++) {
        s[r] = acc[r][0] * as4.x + acc[r][1] * as4.y + acc[r][2] * as4.z + acc[r][3] * as4.w;
        d[r] = acc[r][0] * ad4.x + acc[r][1] * ad4.y + acc[r][2] * ad4.z + acc[r][3] * ad4.w;
    }
#pragma unroll
    for (int r = 0; r < 4; r++) {
        s[r] += __shfl_xor_sync(0xffffffffu, s[r], 1);
        d[r] += __shfl_xor_sync(0xffffffffu, d[r], 1);
        s[r] += __shfl_xor_sync(0xffffffffu, s[r], 2);
        d[r] += __shfl_xor_sync(0xffffffffu, d[r], 2);
    }
    if ((tc & 3) == 0) {
        int head = tc >> 2;
#pragma unroll
        for (int r = 0; r < 4; r++) {
            int row = rowBase + tr * 4 + r;
            if (row < N) {
                g_als1[(size_t)row * 4 + head] = s[r];
                g_ald1[(size_t)row * 4 + head] = d[r];
            }
        }
    }
}

// ---------------- layer-2 folded attention vectors ----------------
__global__ void k_wvec(const float* __restrict__ W2,
                       const float* __restrict__ a_s2, const float* __restrict__ a_d2) {
    int t = threadIdx.x;
    int h = t >> 6, k = t & 63;
    float s = 0.f, d = 0.f;
    for (int c = 0; c < 32; c++) {
        float wv = W2[k * 128 + h * 32 + c];
        s = fmaf(wv, a_s2[h * 32 + c], s);
        d = fmaf(wv, a_d2[h * 32 + c], d);
    }
    g_ws2[t] = s;
    g_wd2[t] = d;
}

// ---------------- fused layer-1 aggregation + layer-2 logits ----------------
__global__ void k_agg1(const float* __restrict__ b1, int N) {
    __shared__ int   sh_idx[8][32];
    __shared__ float sh_ex[8][32 * 4];
    int wid = threadIdx.x >> 5;
    int w = (blockIdx.x * blockDim.x + threadIdx.x) >> 5;
    int lane = threadIdx.x & 31;
    if (w >= N) return;
    int n = w;
    int start = g_rs[n], end = g_rs[n + 1];
    float4 ad = *(const float4*)(g_ald1 + (size_t)n * 4);

    int head = lane >> 3;
    float acc0 = 0.f, acc1 = 0.f;
    float4 den = make_float4(0.f, 0.f, 0.f, 0.f);
    for (int base = start; base < end; base += 32) {
        int i = base + lane;
        int cnt = min(32, end - base);
        int s = 0;
        float4 ex = make_float4(0.f, 0.f, 0.f, 0.f);
        if (i < end) {
            s = g_esrc[i];
            float4 a = *(const float4*)(g_als1 + (size_t)s * 4);
            ex.x = __expf(lrelu(a.x + ad.x));
            ex.y = __expf(lrelu(a.y + ad.y));
            ex.z = __expf(lrelu(a.z + ad.z));
            ex.w = __expf(lrelu(a.w + ad.w));
            den.x += ex.x; den.y += ex.y; den.z += ex.z; den.w += ex.w;
        }
        sh_idx[wid][lane] = s;
        *(float4*)&sh_ex[wid][lane * 4] = ex;
        __syncwarp();
        if (cnt == 32) {
#pragma unroll 8
            for (int j = 0; j < 32; j++) {
                int   sj  = sh_idx[wid][j];
                float exm = sh_ex[wid][j * 4 + head];
                float2 hv = __half22float2(*(const __half2*)(g_h1h + (size_t)sj * 64 + lane * 2));
                acc0 = fmaf(exm, hv.x, acc0);
                acc1 = fmaf(exm, hv.y, acc1);
            }
        } else {
            for (int j = 0; j < cnt; j++) {
                int   sj  = sh_idx[wid][j];
                float exm = sh_ex[wid][j * 4 + head];
                float2 hv = __half22float2(*(const __half2*)(g_h1h + (size_t)sj * 64 + lane * 2));
                acc0 = fmaf(exm, hv.x, acc0);
                acc1 = fmaf(exm, hv.y, acc1);
            }
        }
        __syncwarp();
    }
#pragma unroll
    for (int o = 16; o; o >>= 1) {
        den.x += __shfl_xor_sync(0xffffffffu, den.x, o);
        den.y += __shfl_xor_sync(0xffffffffu, den.y, o);
        den.z += __shfl_xor_sync(0xffffffffu, den.z, o);
        den.w += __shfl_xor_sync(0xffffffffu, den.w, o);
    }
    float dh = (head == 0) ? den.x : ((head == 1) ? den.y : ((head == 2) ? den.z : den.w));
    float inv = 1.f / (dh + 1e-16f);
    float2 o2;
    o2.x = fmaxf(acc0 * inv + b1[lane * 2], 0.f);
    o2.y = fmaxf(acc1 * inv + b1[lane * 2 + 1], 0.f);
    *(__half2*)(g_x2h + (size_t)n * 64 + lane * 2) = __floats2half2_rn(o2.x, o2.y);

    // fused layer-2 logits from fp32 registers
#pragma unroll
    for (int h = 0; h < 4; h++) {
        float2 ws = *(const float2*)(g_ws2 + h * 64 + lane * 2);
        float2 wd = *(const float2*)(g_wd2 + h * 64 + lane * 2);
        float sv = o2.x * ws.x + o2.y * ws.y;
        float dv = o2.x * wd.x + o2.y * wd.y;
#pragma unroll
        for (int o = 16; o; o >>= 1) {
            sv += __shfl_xor_sync(0xffffffffu, sv, o);
            dv += __shfl_xor_sync(0xffffffffu, dv, o);
        }
        if (lane == 0) {
            g_als2[(size_t)n * 4 + h] = sv;
            g_ald2[(size_t)n * 4 + h] = dv;
        }
    }
}

// ---------------- layer-2 aggregation in x2-space (fp16 gather) ----------
__global__ void k_agg2x(int N) {
    __shared__ int   sh_idx[8][32];
    __shared__ float sh_ex[8][32 * 4];
    int wid = threadIdx.x >> 5;
    int w = (blockIdx.x * blockDim.x + threadIdx.x) >> 5;
    int lane = threadIdx.x & 31;
    if (w >= N) return;
    int n = w;
    int start = g_rs[n], end = g_rs[n + 1];
    float4 ad = *(const float4*)(g_ald2 + (size_t)n * 4);

    float a00 = 0.f, a01 = 0.f, a10 = 0.f, a11 = 0.f;
    float a20 = 0.f, a21 = 0.f, a30 = 0.f, a31 = 0.f;
    float4 den = make_float4(0.f, 0.f, 0.f, 0.f);
    for (int base = start; base < end; base += 32) {
        int i = base + lane;
        int cnt = min(32, end - base);
        int s = 0;
        float4 ex = make_float4(0.f, 0.f, 0.f, 0.f);
        if (i < end) {
            s = g_esrc[i];
            float4 a = *(const float4*)(g_als2 + (size_t)s * 4);
            ex.x = __expf(lrelu(a.x + ad.x));
            ex.y = __expf(lrelu(a.y + ad.y));
            ex.z = __expf(lrelu(a.z + ad.z));
            ex.w = __expf(lrelu(a.w + ad.w));
            den.x += ex.x; den.y += ex.y; den.z += ex.z; den.w += ex.w;
        }
        sh_idx[wid][lane] = s;
        *(float4*)&sh_ex[wid][lane * 4] = ex;
        __syncwarp();
        if (cnt == 32) {
#pragma unroll 4
            for (int j = 0; j < 32; j++) {
                int    sj = sh_idx[wid][j];
                float4 e4 = *(const float4*)&sh_ex[wid][j * 4];
                float2 xv = __half22float2(*(const __half2*)(g_x2h + (size_t)sj * 64 + lane * 2));
                a00 = fmaf(e4.x, xv.x, a00); a01 = fmaf(e4.x, xv.y, a01);
                a10 = fmaf(e4.y, xv.x, a10); a11 = fmaf(e4.y, xv.y, a11);
                a20 = fmaf(e4.z, xv.x, a20); a21 = fmaf(e4.z, xv.y, a21);
                a30 = fmaf(e4.w, xv.x, a30); a31 = fmaf(e4.w, xv.y, a31);
            }
        } else {
            for (int j = 0; j < cnt; j++) {
                int    sj = sh_idx[wid][j];
                float4 e4 = *(const float4*)&sh_ex[wid][j * 4];
                float2 xv = __half22float2(*(const __half2*)(g_x2h + (size_t)sj * 64 + lane * 2));
                a00 = fmaf(e4.x, xv.x, a00); a01 = fmaf(e4.x, xv.y, a01);
                a10 = fmaf(e4.y, xv.x, a10); a11 = fmaf(e4.y, xv.y, a11);
                a20 = fmaf(e4.z, xv.x, a20); a21 = fmaf(e4.z, xv.y, a21);
                a30 = fmaf(e4.w, xv.x, a30); a31 = fmaf(e4.w, xv.y, a31);
            }
        }
        __syncwarp();
    }
#pragma unroll
    for (int o = 16; o; o >>= 1) {
        den.x += __shfl_xor_sync(0xffffffffu, den.x, o);
        den.y += __shfl_xor_sync(0xffffffffu, den.y, o);
        den.z += __shfl_xor_sync(0xffffffffu, den.z, o);
        den.w += __shfl_xor_sync(0xffffffffu, den.w, o);
    }
    float i0 = 1.f / (den.x + 1e-16f);
    float i1 = 1.f / (den.y + 1e-16f);
    float i2 = 1.f / (den.z + 1e-16f);
    float i3 = 1.f / (den.w + 1e-16f);
    __half* hg = g_haggh + (size_t)n * 256;
    *(__half2*)(hg +   0 + lane * 2) = __floats2half2_rn(a00 * i0, a01 * i0);
    *(__half2*)(hg +  64 + lane * 2) = __floats2half2_rn(a10 * i1, a11 * i1);
    *(__half2*)(hg + 128 + lane * 2) = __floats2half2_rn(a20 * i2, a21 * i2);
    *(__half2*)(hg + 192 + lane * 2) = __floats2half2_rn(a30 * i3, a31 * i3);
}

// ---------------- post-agg GEMM2 (register-tiled) + bias + relu + pool -------
// Block: 64 rows x 64 cols (grid.y selects col half). 4x4 per thread.
// hagg staged transposed in smem (fp16, rotation-swizzled); W2 half fp32 smem.
__global__ void k_out(const float* __restrict__ W2, const float* __restrict__ b2,
                      const int* __restrict__ batch, int N) {
    __shared__ float  sW[64 * 64];      // [k][c] for this col-half (16KB)
    __shared__ __half sA[2 * 64 * 64];  // [h][k][row rotated] (16KB)
    int tid = threadIdx.x;
    int colBase = blockIdx.y * 64;
    for (int i = tid; i < 64 * 16; i += 256) {
        int k = i >> 4, c4 = i & 15;
        *(float4*)&sW[k * 64 + c4 * 4] =
            __ldg((const float4*)(W2 + k * 128 + colBase + c4 * 4));
    }
    int rowBase = blockIdx.x * 64;
    int h0 = blockIdx.y * 2;
    {
        int lr = tid >> 2;           // row 0..63
        int lq = tid & 3;            // quarter
        int hh = lq >> 1;            // head within pair
        int k0 = (lq & 1) * 32;      // k chunk
        int rot = hh * 8 + (lq & 1) * 16;
        int dstRow = (lr + rot) & 63;
        int row = rowBase + lr;
        if (row < N) {
            const uint2* src = (const uint2*)(g_haggh + (size_t)row * 256 + (h0 + hh) * 64 + k0);
#pragma unroll
            for (int u = 0; u < 8; u++) {
                uint2 v = __ldg(&src[u]);
                __half2 p0 = *(__half2*)&v.x;
                __half2 p1 = *(__half2*)&v.y;
                int k = k0 + u * 4;
                sA[hh * 4096 + (k + 0) * 64 + dstRow] = __low2half(p0);
                sA[hh * 4096 + (k + 1) * 64 + dstRow] = __high2half(p0);
                sA[hh * 4096 + (k + 2) * 64 + dstRow] = __low2half(p1);
                sA[hh * 4096 + (k + 3) * 64 + dstRow] = __high2half(p1);
            }
        } else {
            __half z = __float2half(0.f);
#pragma unroll
            for (int u = 0; u < 8; u++) {
                int k = k0 + u * 4;
                sA[hh * 4096 + (k + 0) * 64 + dstRow] = z;
                sA[hh * 4096 + (k + 1) * 64 + dstRow] = z;
                sA[hh * 4096 + (k + 2) * 64 + dstRow] = z;
                sA[hh * 4096 + (k + 3) * 64 + dstRow] = z;
            }
        }
    }
    __syncthreads();
    int tr = tid >> 4;      // rows tr*4..+3
    int tc = tid & 15;      // cols tc*4..+3
    int head = tc >> 3;     // head within this half
    float acc[4][4] = {};
#pragma unroll
    for (int k = 0; k < 64; k++) {
        int base = (tr * 4 + head * 8 + (k >> 5) * 16) & 63;
        uint2 av = *(const uint2*)&sA[head * 4096 + k * 64 + base];
        float2 a01 = __half22float2(*(const __half2*)&av.x);
        float2 a23 = __half22float2(*(const __half2*)&av.y);
        float4 w4 = *(const float4*)&sW[k * 64 + tc * 4];
        acc[0][0] = fmaf(a01.x, w4.x, acc[0][0]); acc[0][1] = fmaf(a01.x, w4.y, acc[0][1]);
        acc[0][2] = fmaf(a01.x, w4.z, acc[0][2]); acc[0][3] = fmaf(a01.x, w4.w, acc[0][3]);
        acc[1][0] = fmaf(a01.y, w4.x, acc[1][0]); acc[1][1] = fmaf(a01.y, w4.y, acc[1][1]);
        acc[1][2] = fmaf(a01.y, w4.z, acc[1][2]); acc[1][3] = fmaf(a01.y, w4.w, acc[1][3]);
        acc[2][0] = fmaf(a23.x, w4.x, acc[2][0]); acc[2][1] = fmaf(a23.x, w4.y, acc[2][1]);
        acc[2][2] = fmaf(a23.x, w4.z, acc[2][2]); acc[2][3] = fmaf(a23.x, w4.w, acc[2][3]);
        acc[3][0] = fmaf(a23.y, w4.x, acc[3][0]); acc[3][1] = fmaf(a23.y, w4.y, acc[3][1]);
        acc[3][2] = fmaf(a23.y, w4.z, acc[3][2]); acc[3][3] = fmaf(a23.y, w4.w, acc[3][3]);
    }
    const float4 bb = __ldg((const float4*)(b2 + colBase + tc * 4));
#pragma unroll
    for (int r = 0; r < 4; r++) {
        int row = rowBase + tr * 4 + r;
        if (row < N) {
            float o0 = fmaxf(acc[r][0] + bb.x, 0.f);
            float o1 = fmaxf(acc[r][1] + bb.y, 0.f);
            float o2 = fmaxf(acc[r][2] + bb.z, 0.f);
            float o3 = fmaxf(acc[r][3] + bb.w, 0.f);
            int g = __ldg(&batch[row]);
            red4(g_sums + (size_t)g * 128 + colBase + tc * 4, o0, o1, o2, o3);
            if (tc == 0 && blockIdx.y == 0) atomicAdd(&g_cnt[g], 1.f);
        }
    }
}

// ---------------- pool divide ----------------
__global__ void k_pool(float* __restrict__ out, int G) {
    int t = blockIdx.x * blockDim.x + threadIdx.x;
    if (t >= G * 32) return;
    int g = t >> 5;
    float inv = 1.f / fmaxf(g_cnt[g], 1.f);
    float4 s = *(const float4*)(g_sums + (size_t)t * 4);
    float4 o = { s.x * inv, s.y * inv, s.z * inv, s.w * inv };
    *(float4*)(out + (size_t)t * 4) = o;
}

// ---------------- launch ----------------
extern "C" void kernel_launch(void* const* d_in, const int* in_sizes, int n_in,
                              void* d_out, int out_size) {
    const float* x     = (const float*)d_in[0];
    const int*   ei    = (const int*)d_in[1];
    const int*   batch = (const int*)d_in[3];
    const float* W1    = (const float*)d_in[4];
    const float* a_s1  = (const float*)d_in[5];
    const float* a_d1  = (const float*)d_in[6];
    const float* b1    = (const float*)d_in[7];
    const float* W2    = (const float*)d_in[8];
    const float* a_s2  = (const float*)d_in[9];
    const float* a_d2  = (const float*)d_in[10];
    const float* b2    = (const float*)d_in[11];
    float*       out   = (float*)d_out;

    int N = in_sizes[0] / 128;
    int E = in_sizes[1] / 2;
    int G = out_size / 128;
    int T = E + N;

    void *pdeg, *ps, *pc;
    cudaGetSymbolAddress(&pdeg, g_deg);
    cudaGetSymbolAddress(&ps, g_sums);
    cudaGetSymbolAddress(&pc, g_cnt);

    // fork a non-blocking side stream for the CSR-independent GEMM work
    cudaStream_t s2;
    cudaStreamCreateWithFlags(&s2, cudaStreamNonBlocking);
    cudaEvent_t eFork, eJoin;
    cudaEventCreateWithFlags(&eFork, cudaEventDisableTiming);
    cudaEventCreateWithFlags(&eJoin, cudaEventDisableTiming);

    cudaEventRecord(eFork, 0);
    cudaStreamWaitEvent(s2, eFork, 0);

    // side stream: fold W2@a2, then GEMM1 (+logits)
    k_wvec<<<1, 256, 0, s2>>>(W2, a_s2, a_d2);
    k_gemm1<<<(N + 63) / 64, 256, 0, s2>>>(x, W1, a_s1, a_d1, N);
    cudaEventRecord(eJoin, s2);

    // main stream: memsets + CSR build
    cudaMemsetAsync(pdeg, 0, (size_t)N * 4);
    cudaMemsetAsync(ps, 0, (size_t)G * 128 * 4);
    cudaMemsetAsync(pc, 0, (size_t)G * 4);

    int nb = (N + 255) / 256;
    k_deg<<<(E + 255) / 256, 256>>>(ei, E);
    k_s1<<<nb, 256>>>(N);
    k_s2<<<1, 512>>>(nb);
    k_s3<<<(N + 256) / 256, 256>>>(N, T);
    k_fill<<<(T + 255) / 256, 256>>>(ei, E, N);

    // join: aggregation needs both CSR and GEMM1 results
    cudaStreamWaitEvent(0, eJoin, 0);

    k_agg1<<<(N + 7) / 8, 256>>>(b1, N);
    k_agg2x<<<(N + 7) / 8, 256>>>(N);
    {
        dim3 grid((N + 63) / 64, 2);
        k_out<<<grid, 256>>>(W2, b2, batch, N);
    }
    k_pool<<<(G * 32 + 255) / 256, 256>>>(out, G);

    // NOTE: stream/event objects are intentionally not destroyed here —
    // destroying capture-referenced objects mid-capture is invalid, and
    // kernel_launch runs only a handful of times (host-side leak only).
}